// round 8
// baseline (speedup 1.0000x reference)
#include <cuda_runtime.h>
#include <math.h>

#define BB 64
#define CC 2048
#define QQ 128
#define DD 128
#define CT 64
#define NSPLIT 4
#define MASKV (-1e30f)
#define SAP 132   // A-tile word stride
#define SBP 136   // B-tile word stride
#define STS 20    // mid stT stride

// ----------------------------------------------------------------------------
// Device scratch
// ----------------------------------------------------------------------------
__device__ float g_score[(size_t)BB * CC * QQ];   // stores E = exp(raw score)
__device__ float g_rc[BB * CC];
__device__ float g_cq[BB * QQ];
__device__ float g_colsum[BB * QQ];               // sum_c E * vmask
__device__ float g_mid[BB * QQ * DD];             // unscaled: sum_c E*vmask*v
__device__ float g_pproj[BB * DD];
__device__ float g_qfT[BB * DD * QQ];
__device__ float g_cqaWT[4 * DD * DD];
__device__ float g_ccWT[DD * DD];

// ----------------------------------------------------------------------------
// TF32 MMA helpers (3xTF32 split)
// ----------------------------------------------------------------------------
__device__ __forceinline__ void mma_tf32(float c[4], const unsigned a[4], const unsigned b[2]) {
    asm volatile(
        "mma.sync.aligned.m16n8k8.row.col.f32.tf32.tf32.f32 "
        "{%0,%1,%2,%3}, {%4,%5,%6,%7}, {%8,%9}, {%0,%1,%2,%3};"
        : "+f"(c[0]), "+f"(c[1]), "+f"(c[2]), "+f"(c[3])
        : "r"(a[0]), "r"(a[1]), "r"(a[2]), "r"(a[3]), "r"(b[0]), "r"(b[1]));
}

__device__ __forceinline__ unsigned f2tf(float x) {
    unsigned r;
    asm("cvt.rna.tf32.f32 %0, %1;" : "=r"(r) : "f"(x));
    return r;
}

__device__ __forceinline__ void tf_split(float x, unsigned& h, unsigned& l) {
    h = f2tf(x);
    l = f2tf(x - __uint_as_float(h));
}

template <int NT, bool PROD, int SA, int SB, int K>
__device__ __forceinline__ void mma_stage(const float* __restrict__ A,
                                          const float* __restrict__ A2,
                                          const float* __restrict__ B,
                                          float acc[2][NT][4],
                                          int wr0, int wc0, int lane) {
    const int gr = lane >> 2, tg = lane & 3;
#pragma unroll 2
    for (int k0 = 0; k0 < K; k0 += 8) {
        unsigned ah[2][4], al[2][4];
#pragma unroll
        for (int rb = 0; rb < 2; rb++) {
            const float* p0 = A + (wr0 + rb * 16 + gr) * SA + k0 + tg;
            const float* p1 = A + (wr0 + rb * 16 + 8 + gr) * SA + k0 + tg;
            float v0 = p0[0], v1 = p1[0], v2 = p0[4], v3 = p1[4];
            if (PROD) {
                const float* q0 = A2 + (wr0 + rb * 16 + gr) * SA + k0 + tg;
                const float* q1 = A2 + (wr0 + rb * 16 + 8 + gr) * SA + k0 + tg;
                v0 *= q0[0]; v1 *= q1[0]; v2 *= q0[4]; v3 *= q1[4];
            }
            tf_split(v0, ah[rb][0], al[rb][0]);
            tf_split(v1, ah[rb][1], al[rb][1]);
            tf_split(v2, ah[rb][2], al[rb][2]);
            tf_split(v3, ah[rb][3], al[rb][3]);
        }
#pragma unroll
        for (int nt = 0; nt < NT; nt++) {
            int n = wc0 + nt * 8 + gr;
            float b0 = B[(k0 + tg) * SB + n];
            float b1 = B[(k0 + 4 + tg) * SB + n];
            unsigned bh[2], bl[2];
            tf_split(b0, bh[0], bl[0]);
            tf_split(b1, bh[1], bl[1]);
#pragma unroll
            for (int rb = 0; rb < 2; rb++) {
                mma_tf32(acc[rb][nt], ah[rb], bh);
                mma_tf32(acc[rb][nt], al[rb], bh);
                mma_tf32(acc[rb][nt], ah[rb], bl);
            }
        }
    }
}

// ----------------------------------------------------------------------------
// Prep kernels
// ----------------------------------------------------------------------------
__global__ void prep_w(const float* __restrict__ cqa_W, const float* __restrict__ cc_W) {
    int i = blockIdx.x * blockDim.x + threadIdx.x;
    if (i < 4 * DD * DD) {
        int p = i / (DD * DD);
        int r = i % (DD * DD);
        int k = r / DD, d = r % DD;
        g_cqaWT[i] = cqa_W[d * (4 * DD) + p * DD + k];
    }
    if (i < DD * DD) {
        int k = i / DD, d = i % DD;
        g_ccWT[i] = cc_W[d * (2 * DD) + k];
    }
}

__global__ void prep_qfT(const float* __restrict__ qf) {
    int i = blockIdx.x * blockDim.x + threadIdx.x;
    if (i >= BB * DD * QQ) return;
    int q = i % QQ;
    int t = i / QQ;
    int d = t % DD;
    int b = t / DD;
    g_qfT[i] = qf[((size_t)(b * QQ + q)) * DD + d];
}

__global__ void prep_rc_cq(const float* __restrict__ vf, const float* __restrict__ qf,
                           const float* __restrict__ w4C, const float* __restrict__ w4Q) {
    int i = blockIdx.x * blockDim.x + threadIdx.x;
    if (i < BB * CC) {
        const float* row = vf + (size_t)i * DD;
        float s = 0.f;
#pragma unroll 4
        for (int d = 0; d < DD; d++) s += row[d] * w4C[d];
        g_rc[i] = s;
    }
    if (i < BB * QQ) {
        const float* row = qf + (size_t)i * DD;
        float s = 0.f;
#pragma unroll 4
        for (int d = 0; d < DD; d++) s += row[d] * w4Q[d];
        g_cq[i] = s;
    }
}

__global__ void zero_k() {
    int i = blockIdx.x * blockDim.x + threadIdx.x;
    if (i < BB * QQ * DD) g_mid[i] = 0.f;
    if (i < BB * QQ) g_colsum[i] = 0.f;
}

// ----------------------------------------------------------------------------
// Pooled query projection
// ----------------------------------------------------------------------------
__global__ void pooled_kernel(const float* __restrict__ qf, const float* __restrict__ qmask,
                              const float* __restrict__ wp, const float* __restrict__ cc_W,
                              const float* __restrict__ cc_b) {
    __shared__ float sred[QQ];
    __shared__ float s_al[QQ];
    __shared__ float s_pool[DD];
    int b = blockIdx.x, t = threadIdx.x;

    const float* row = qf + (size_t)(b * QQ + t) * DD;
    float x = 0.f;
#pragma unroll 4
    for (int d = 0; d < DD; d++) x += row[d] * wp[d];
    x += (1.f - qmask[b * QQ + t]) * MASKV;

    sred[t] = x; __syncthreads();
    for (int s = 64; s > 0; s >>= 1) {
        if (t < s) sred[t] = fmaxf(sred[t], sred[t + s]);
        __syncthreads();
    }
    float m = sred[0]; __syncthreads();
    float e = __expf(x - m);
    sred[t] = e; __syncthreads();
    for (int s = 64; s > 0; s >>= 1) {
        if (t < s) sred[t] += sred[t + s];
        __syncthreads();
    }
    float inv = 1.f / sred[0];
    s_al[t] = e * inv; __syncthreads();

    float p = 0.f;
#pragma unroll 4
    for (int q = 0; q < QQ; q++) p += s_al[q] * qf[(size_t)(b * QQ + q) * DD + t];
    s_pool[t] = p; __syncthreads();

    float o = cc_b[t];
#pragma unroll 4
    for (int k = 0; k < DD; k++) o += s_pool[k] * cc_W[t * (2 * DD) + DD + k];
    g_pproj[b * DD + t] = o;
}

// ----------------------------------------------------------------------------
// Score kernel: E = exp(score), plus column-sum accumulation (E * vmask)
// ----------------------------------------------------------------------------
__global__ __launch_bounds__(256) void score_kernel(const float* __restrict__ vf,
                                                    const float* __restrict__ vmask,
                                                    const float* __restrict__ w4mlu) {
    extern __shared__ float sm[];
    float* sA = sm;                   // [64][SAP]
    float* sB = sA + CT * SAP;        // [128][SBP]
    float* s_mlu = sB + DD * SBP;     // [128]

    int b = blockIdx.y, c0 = blockIdx.x * CT, tid = threadIdx.x;
    if (tid < DD) s_mlu[tid] = w4mlu[tid];
    __syncthreads();

    {
        const float* src = vf + (size_t)(b * CC + c0) * DD;
        for (int i = tid; i < CT * DD; i += 256) {
            int r = i >> 7, c = i & 127;
            sA[r * SAP + c] = src[i] * s_mlu[c];
        }
        const float* qs = g_qfT + (size_t)b * DD * QQ;
        for (int i = tid; i < DD * QQ; i += 256) {
            int d = i >> 7, q = i & 127;
            sB[d * SBP + q] = qs[i];
        }
    }
    __syncthreads();

    int warp = tid >> 5, lane = tid & 31;
    int gr = lane >> 2, tg = lane & 3;
    int wr0 = (warp & 1) * 32, wc0 = (warp >> 1) * 32;

    float acc[2][4][4];
#pragma unroll
    for (int rb = 0; rb < 2; rb++)
#pragma unroll
        for (int nt = 0; nt < 4; nt++)
#pragma unroll
            for (int j = 0; j < 4; j++) acc[rb][nt][j] = 0.f;

    mma_stage<4, false, SAP, SBP, 128>(sA, nullptr, sB, acc, wr0, wc0, lane);

    // epilogue: E = exp(score), store, and gather masked column sums
    float vm[4];
    vm[0] = vmask[b * CC + c0 + wr0 + gr];
    vm[1] = vmask[b * CC + c0 + wr0 + gr + 8];
    vm[2] = vmask[b * CC + c0 + wr0 + gr + 16];
    vm[3] = vmask[b * CC + c0 + wr0 + gr + 24];

#pragma unroll
    for (int rb = 0; rb < 2; rb++) {
        int r = wr0 + rb * 16 + gr;
        float rc0 = g_rc[b * CC + c0 + r];
        float rc1 = g_rc[b * CC + c0 + r + 8];
#pragma unroll
        for (int nt = 0; nt < 4; nt++) {
            int q = wc0 + nt * 8 + 2 * tg;
            float cq0 = g_cq[b * QQ + q], cq1 = g_cq[b * QQ + q + 1];
            acc[rb][nt][0] = __expf(acc[rb][nt][0] + rc0 + cq0);
            acc[rb][nt][1] = __expf(acc[rb][nt][1] + rc0 + cq1);
            acc[rb][nt][2] = __expf(acc[rb][nt][2] + rc1 + cq0);
            acc[rb][nt][3] = __expf(acc[rb][nt][3] + rc1 + cq1);
            float* d0 = g_score + ((size_t)(b * CC + c0 + r)) * QQ + q;
            float* d1 = g_score + ((size_t)(b * CC + c0 + r + 8)) * QQ + q;
            *(float2*)d0 = make_float2(acc[rb][nt][0], acc[rb][nt][1]);
            *(float2*)d1 = make_float2(acc[rb][nt][2], acc[rb][nt][3]);
        }
    }

#pragma unroll
    for (int nt = 0; nt < 4; nt++) {
#pragma unroll
        for (int j = 0; j < 2; j++) {
            float cs = acc[0][nt][j] * vm[0] + acc[0][nt][j + 2] * vm[1] +
                       acc[1][nt][j] * vm[2] + acc[1][nt][j + 2] * vm[3];
            cs += __shfl_xor_sync(0xffffffffu, cs, 4);
            cs += __shfl_xor_sync(0xffffffffu, cs, 8);
            cs += __shfl_xor_sync(0xffffffffu, cs, 16);
            if (lane < 4)
                atomicAdd(&g_colsum[b * QQ + wc0 + nt * 8 + 2 * tg + j], cs);
        }
    }
}

// ----------------------------------------------------------------------------
// mid(unscaled)[q,d] = sum_c E[c,q]*vmask[c]*v[c,d]  (MMA split-K + atomicAdd)
// ----------------------------------------------------------------------------
__global__ __launch_bounds__(256) void mid_kernel(const float* __restrict__ vf,
                                                  const float* __restrict__ vmask) {
    __shared__ float s_stT[QQ * STS];   // [q][kc]
    __shared__ float s_v[16 * SBP];     // [kc][d]
    int b = blockIdx.x, sp = blockIdx.y, tid = threadIdx.x;
    int cbase = sp * (CC / NSPLIT);
    int warp = tid >> 5, lane = tid & 31;
    int gr = lane >> 2, tg = lane & 3;
    int wr0 = (warp & 3) * 32, wc0 = (warp >> 2) * 64;

    float acc[2][8][4];
#pragma unroll
    for (int rb = 0; rb < 2; rb++)
#pragma unroll
        for (int nt = 0; nt < 8; nt++)
#pragma unroll
            for (int j = 0; j < 4; j++) acc[rb][nt][j] = 0.f;

    for (int cc0 = 0; cc0 < CC / NSPLIT; cc0 += 16) {
        __syncthreads();
        for (int i = tid; i < 16 * QQ; i += 256) {
            int kc = i >> 7, col = i & 127;
            int c = cbase + cc0 + kc;
            float e = g_score[((size_t)(b * CC + c)) * QQ + col];
            s_stT[col * STS + kc] = e * vmask[b * CC + c];
            s_v[kc * SBP + col] = vf[((size_t)(b * CC + c)) * DD + col];
        }
        __syncthreads();
        mma_stage<8, false, STS, SBP, 16>(s_stT, nullptr, s_v, acc, wr0, wc0, lane);
    }

#pragma unroll
    for (int rb = 0; rb < 2; rb++) {
        int q = wr0 + rb * 16 + gr;
#pragma unroll
        for (int nt = 0; nt < 8; nt++) {
            int d = wc0 + nt * 8 + 2 * tg;
            atomicAdd(&g_mid[(size_t)(b * QQ + q) * DD + d],     acc[rb][nt][0]);
            atomicAdd(&g_mid[(size_t)(b * QQ + q) * DD + d + 1], acc[rb][nt][1]);
            atomicAdd(&g_mid[(size_t)(b * QQ + q + 8) * DD + d],     acc[rb][nt][2]);
            atomicAdd(&g_mid[(size_t)(b * QQ + q + 8) * DD + d + 1], acc[rb][nt][3]);
        }
    }
}

// ----------------------------------------------------------------------------
// Mega-fused: row softmax (no exp) -> c2q -> q2c -> cat@cqa_W.T -> final + ReLU
// ----------------------------------------------------------------------------
__global__ __launch_bounds__(256, 1) void fused_kernel(const float* __restrict__ vf,
                                                       const float* __restrict__ qf,
                                                       const float* __restrict__ qmask,
                                                       const float* __restrict__ cqa_b,
                                                       float* __restrict__ out) {
    extern __shared__ float sm[];
    float* s_sc  = sm;                   // [64][SAP] score_ then feats
    float* s_v   = s_sc + CT * SAP;      // [64][SAP]
    float* s_c2q = s_v + CT * SAP;       // [64][SAP]
    float* s_q2c = s_c2q + CT * SAP;     // [64][SAP]
    float* s_B   = s_q2c + CT * SAP;     // [128][SBP]
    float* s_ci  = s_B + DD * SBP;       // [128] 1/colsum

    int b = blockIdx.y;
    int c0 = blockIdx.x * CT;
    int tid = threadIdx.x;
    int warp = tid >> 5, lane = tid & 31;
    int gr = lane >> 2, tg = lane & 3;
    int wr0 = (warp & 1) * 32, wc0 = (warp >> 1) * 32;

    if (tid < QQ) s_ci[tid] = 1.f / g_colsum[b * QQ + tid];

    // Row softmax from E: em = E*qmask; s_sc = em / sum(em)   (no exp, no max)
    {
        float qm[4];
#pragma unroll
        for (int j = 0; j < 4; j++) qm[j] = qmask[b * QQ + lane + 32 * j];
#pragma unroll
        for (int rr = 0; rr < 8; rr++) {
            int r = warp * 8 + rr;
            const float* src = g_score + ((size_t)(b * CC + c0 + r)) * QQ;
            float em[4];
            float s = 0.f;
#pragma unroll
            for (int j = 0; j < 4; j++) { em[j] = src[lane + 32 * j] * qm[j]; s += em[j]; }
#pragma unroll
            for (int off = 16; off > 0; off >>= 1)
                s += __shfl_xor_sync(0xffffffffu, s, off);
            float inv = 1.f / s;
#pragma unroll
            for (int j = 0; j < 4; j++) s_sc[r * SAP + lane + 32 * j] = em[j] * inv;
        }
    }
    // load v tile (A-format) and qfeats (B-format)
    {
        const float* src = vf + ((size_t)(b * CC + c0)) * DD;
        for (int i = tid; i < CT * DD; i += 256)
            s_v[(i >> 7) * SAP + (i & 127)] = src[i];
        const float* qs = qf + (size_t)b * QQ * DD;
        for (int i = tid; i < QQ * DD; i += 256)
            s_B[(i >> 7) * SBP + (i & 127)] = qs[i];
    }
    __syncthreads();

    float acc[2][4][4];
#define ZERO_ACC(A_)                                      \
    _Pragma("unroll") for (int rb = 0; rb < 2; rb++)      \
    _Pragma("unroll") for (int nt = 0; nt < 4; nt++)      \
    _Pragma("unroll") for (int j = 0; j < 4; j++) A_[rb][nt][j] = 0.f;

#define STORE_ACC(DST, A_)                                                      \
    _Pragma("unroll") for (int rb = 0; rb < 2; rb++) {                          \
        int r_ = wr0 + rb * 16 + gr;                                            \
        _Pragma("unroll") for (int nt = 0; nt < 4; nt++) {                      \
            int cI = wc0 + nt * 8 + 2 * tg;                                     \
            (DST)[r_ * SAP + cI]       = A_[rb][nt][0];                         \
            (DST)[r_ * SAP + cI + 1]   = A_[rb][nt][1];                         \
            (DST)[(r_ + 8) * SAP + cI]     = A_[rb][nt][2];                     \
            (DST)[(r_ + 8) * SAP + cI + 1] = A_[rb][nt][3];                     \
        }                                                                       \
    }

    // GEMM1: c2q = score_ @ qfeats
    ZERO_ACC(acc)
    mma_stage<4, false, SAP, SBP, 128>(s_sc, nullptr, s_B, acc, wr0, wc0, lane);
    STORE_ACC(s_c2q, acc)
    __syncthreads();

    // GEMM2: q2c = score_ @ (mid * colinv)
    {
        const float* src = g_mid + (size_t)b * QQ * DD;
        for (int i = tid; i < QQ * DD; i += 256) {
            int q = i >> 7;
            s_B[q * SBP + (i & 127)] = src[i] * s_ci[q];
        }
    }
    __syncthreads();
    ZERO_ACC(acc)
    mma_stage<4, false, SAP, SBP, 128>(s_sc, nullptr, s_B, acc, wr0, wc0, lane);
    STORE_ACC(s_q2c, acc)
    __syncthreads();

    // feats = [v, c2q, v*c2q, v*q2c] @ cqa_W.T + cqa_b
    float facc[2][4][4];
#pragma unroll
    for (int rb = 0; rb < 2; rb++)
#pragma unroll
        for (int nt = 0; nt < 4; nt++) {
            int d = wc0 + nt * 8 + 2 * tg;
            float b0 = cqa_b[d], b1 = cqa_b[d + 1];
            facc[rb][nt][0] = b0; facc[rb][nt][1] = b1;
            facc[rb][nt][2] = b0; facc[rb][nt][3] = b1;
        }
#pragma unroll 1
    for (int part = 0; part < 4; part++) {
        const float* src = g_cqaWT + part * DD * DD;
        for (int i = tid; i < DD * DD; i += 256)
            s_B[(i >> 7) * SBP + (i & 127)] = src[i];
        __syncthreads();
        if (part == 0)
            mma_stage<4, false, SAP, SBP, 128>(s_v, nullptr, s_B, facc, wr0, wc0, lane);
        else if (part == 1)
            mma_stage<4, false, SAP, SBP, 128>(s_c2q, nullptr, s_B, facc, wr0, wc0, lane);
        else if (part == 2)
            mma_stage<4, true, SAP, SBP, 128>(s_v, s_c2q, s_B, facc, wr0, wc0, lane);
        else
            mma_stage<4, true, SAP, SBP, 128>(s_v, s_q2c, s_B, facc, wr0, wc0, lane);
        __syncthreads();
    }

    // feats -> s_sc, load ccWT
    STORE_ACC(s_sc, facc)
    for (int i = tid; i < DD * DD; i += 256)
        s_B[(i >> 7) * SBP + (i & 127)] = g_ccWT[i];
    __syncthreads();

    // out = relu(feats @ cc_W[:, :D].T + pproj)
    float oacc[2][4][4];
#pragma unroll
    for (int rb = 0; rb < 2; rb++)
#pragma unroll
        for (int nt = 0; nt < 4; nt++) {
            int d = wc0 + nt * 8 + 2 * tg;
            float p0 = g_pproj[b * DD + d], p1 = g_pproj[b * DD + d + 1];
            oacc[rb][nt][0] = p0; oacc[rb][nt][1] = p1;
            oacc[rb][nt][2] = p0; oacc[rb][nt][3] = p1;
        }
    mma_stage<4, false, SAP, SBP, 128>(s_sc, nullptr, s_B, oacc, wr0, wc0, lane);

#pragma unroll
    for (int rb = 0; rb < 2; rb++) {
        int r = wr0 + rb * 16 + gr;
#pragma unroll
        for (int nt = 0; nt < 4; nt++) {
            int d = wc0 + nt * 8 + 2 * tg;
            float* d0 = out + ((size_t)(b * CC + c0 + r)) * DD + d;
            float* d1 = out + ((size_t)(b * CC + c0 + r + 8)) * DD + d;
            *(float2*)d0 = make_float2(fmaxf(oacc[rb][nt][0], 0.f), fmaxf(oacc[rb][nt][1], 0.f));
            *(float2*)d1 = make_float2(fmaxf(oacc[rb][nt][2], 0.f), fmaxf(oacc[rb][nt][3], 0.f));
        }
    }
}

// ----------------------------------------------------------------------------
// Launch
// ----------------------------------------------------------------------------
extern "C" void kernel_launch(void* const* d_in, const int* in_sizes, int n_in,
                              void* d_out, int out_size) {
    const float* vfeats = (const float*)d_in[0];
    const float* qfeats = (const float*)d_in[1];
    const float* vmask  = (const float*)d_in[2];
    const float* qmask  = (const float*)d_in[3];
    const float* w4C    = (const float*)d_in[4];
    const float* w4Q    = (const float*)d_in[5];
    const float* w4mlu  = (const float*)d_in[6];
    const float* cqa_W  = (const float*)d_in[7];
    const float* cqa_b  = (const float*)d_in[8];
    const float* wp     = (const float*)d_in[9];
    const float* cc_W   = (const float*)d_in[10];
    const float* cc_b   = (const float*)d_in[11];
    float* out = (float*)d_out;

    const int SCORE_SMEM = (CT * SAP + DD * SBP + DD) * (int)sizeof(float);
    const int FUSED_SMEM = (4 * CT * SAP + DD * SBP + DD) * (int)sizeof(float);
    cudaFuncSetAttribute(score_kernel, cudaFuncAttributeMaxDynamicSharedMemorySize, SCORE_SMEM);
    cudaFuncSetAttribute(fused_kernel, cudaFuncAttributeMaxDynamicSharedMemorySize, FUSED_SMEM);

    prep_w<<<(4 * DD * DD + 255) / 256, 256>>>(cqa_W, cc_W);
    prep_qfT<<<(BB * DD * QQ + 255) / 256, 256>>>(qfeats);
    prep_rc_cq<<<(BB * CC + 255) / 256, 256>>>(vfeats, qfeats, w4C, w4Q);
    zero_k<<<(BB * QQ * DD + 255) / 256, 256>>>();
    pooled_kernel<<<BB, QQ>>>(qfeats, qmask, wp, cc_W, cc_b);
    score_kernel<<<dim3(CC / CT, BB), 256, SCORE_SMEM>>>(vfeats, vmask, w4mlu);
    mid_kernel<<<dim3(BB, NSPLIT), 256>>>(vfeats, vmask);
    fused_kernel<<<dim3(CC / CT, BB), 256, FUSED_SMEM>>>(vfeats, qfeats, qmask, cqa_b, out);
}

// round 9
// speedup vs baseline: 1.1447x; 1.1447x over previous
#include <cuda_runtime.h>
#include <cuda_bf16.h>
#include <math.h>

#define BB 64
#define CC 2048
#define QQ 128
#define DD 128
#define CT 64
#define NSPLIT 4
#define MASKV (-1e30f)
#define SA 132    // packed A-tile word stride (score/fused)
#define SB 136    // packed B-tile word stride
#define SMA 18    // mid stT word stride

// ----------------------------------------------------------------------------
// Device scratch
// ----------------------------------------------------------------------------
__device__ float    g_score[(size_t)BB * CC * QQ];  // E = exp(raw score)
__device__ float    g_rc[BB * CC];
__device__ float    g_cq[BB * QQ];
__device__ float    g_colsum[BB * QQ];
__device__ float    g_mid[BB * QQ * DD];            // unscaled sum_c E*vmask*v
__device__ float    g_pproj[BB * DD];
__device__ unsigned g_midp[BB * QQ * DD];           // packed (mid/colsum)
__device__ unsigned g_qfTp[BB * DD * QQ];           // packed qfeats^T [b][d][q]
__device__ unsigned g_qfp[BB * QQ * DD];            // packed qfeats  [b][q][d]
__device__ unsigned g_vfp[(size_t)BB * CC * DD];    // packed vfeats
__device__ unsigned g_vmlup[(size_t)BB * CC * DD];  // packed vfeats*w4mlu
__device__ unsigned g_cqaWTp[4 * DD * DD];          // packed [part][k][d]
__device__ unsigned g_ccWTp[DD * DD];               // packed [k][d]

// ----------------------------------------------------------------------------
// bf16-split helpers
// ----------------------------------------------------------------------------
__device__ __forceinline__ unsigned pack_bf(float x) {
    unsigned h = (unsigned)__bfloat16_as_ushort(__float2bfloat16(x));
    float hf = __uint_as_float(h << 16);
    unsigned l = (unsigned)__bfloat16_as_ushort(__float2bfloat16(x - hf));
    return h | (l << 16);
}

__device__ __forceinline__ void mma_bf16(float c[4], const unsigned a[4], const unsigned b[2]) {
    asm volatile(
        "mma.sync.aligned.m16n8k16.row.col.f32.bf16.bf16.f32 "
        "{%0,%1,%2,%3}, {%4,%5,%6,%7}, {%8,%9}, {%0,%1,%2,%3};"
        : "+f"(c[0]), "+f"(c[1]), "+f"(c[2]), "+f"(c[3])
        : "r"(a[0]), "r"(a[1]), "r"(a[2]), "r"(a[3]), "r"(b[0]), "r"(b[1]));
}

// Warp computes C[wr0:wr0+32][wc0:wc0+NT*8] += A @ B from packed smem.
// A row-major [m][k] (word = (hi,lo) of one element), stride SAs;
// B [k][n] stride SBs. 3-term split: AhBh + AlBh + AhBl.
template <int NT, int SAs, int SBs, int K>
__device__ __forceinline__ void mma_stage_p(const unsigned* __restrict__ A,
                                            const unsigned* __restrict__ B,
                                            float acc[2][NT][4],
                                            int wr0, int wc0, int lane) {
    const int gr = lane >> 2, t2 = (lane & 3) * 2;
#pragma unroll
    for (int k0 = 0; k0 < K; k0 += 16) {
        unsigned ah[2][4], al[2][4];
#pragma unroll
        for (int rb = 0; rb < 2; rb++) {
            const unsigned* p0 = A + (wr0 + rb * 16 + gr) * SAs + k0 + t2;
            const unsigned* p1 = A + (wr0 + rb * 16 + 8 + gr) * SAs + k0 + t2;
            uint2 wa = *(const uint2*)p0;
            uint2 wb = *(const uint2*)p1;
            uint2 wc = *(const uint2*)(p0 + 8);
            uint2 wd = *(const uint2*)(p1 + 8);
            ah[rb][0] = __byte_perm(wa.x, wa.y, 0x5410); al[rb][0] = __byte_perm(wa.x, wa.y, 0x7632);
            ah[rb][1] = __byte_perm(wb.x, wb.y, 0x5410); al[rb][1] = __byte_perm(wb.x, wb.y, 0x7632);
            ah[rb][2] = __byte_perm(wc.x, wc.y, 0x5410); al[rb][2] = __byte_perm(wc.x, wc.y, 0x7632);
            ah[rb][3] = __byte_perm(wd.x, wd.y, 0x5410); al[rb][3] = __byte_perm(wd.x, wd.y, 0x7632);
        }
#pragma unroll
        for (int nt = 0; nt < NT; nt++) {
            int n = wc0 + nt * 8 + gr;
            unsigned v0 = B[(k0 + t2) * SBs + n];
            unsigned v1 = B[(k0 + t2 + 1) * SBs + n];
            unsigned v2 = B[(k0 + 8 + t2) * SBs + n];
            unsigned v3 = B[(k0 + 9 + t2) * SBs + n];
            unsigned bh[2] = {__byte_perm(v0, v1, 0x5410), __byte_perm(v2, v3, 0x5410)};
            unsigned bl[2] = {__byte_perm(v0, v1, 0x7632), __byte_perm(v2, v3, 0x7632)};
#pragma unroll
            for (int rb = 0; rb < 2; rb++) {
                mma_bf16(acc[rb][nt], ah[rb], bh);
                mma_bf16(acc[rb][nt], al[rb], bh);
                mma_bf16(acc[rb][nt], ah[rb], bl);
            }
        }
    }
}

// ----------------------------------------------------------------------------
// Prep kernels
// ----------------------------------------------------------------------------
__global__ void prep_w(const float* __restrict__ cqa_W, const float* __restrict__ cc_W) {
    int i = blockIdx.x * blockDim.x + threadIdx.x;
    if (i < 4 * DD * DD) {
        int p = i / (DD * DD);
        int r = i % (DD * DD);
        int k = r / DD, d = r % DD;
        g_cqaWTp[i] = pack_bf(cqa_W[d * (4 * DD) + p * DD + k]);
    }
    if (i < DD * DD) {
        int k = i / DD, d = i % DD;
        g_ccWTp[i] = pack_bf(cc_W[d * (2 * DD) + k]);
    }
}

__global__ void prep_qf(const float* __restrict__ qf) {
    int i = blockIdx.x * blockDim.x + threadIdx.x;
    if (i >= BB * DD * QQ) return;
    int q = i % QQ;
    int t = i / QQ;
    int d = t % DD;
    int b = t / DD;
    g_qfTp[i] = pack_bf(qf[((size_t)(b * QQ + q)) * DD + d]);
    g_qfp[i] = pack_bf(qf[i]);
}

__global__ void prep_vf(const float* __restrict__ vf, const float* __restrict__ w4mlu) {
    size_t i = (size_t)blockIdx.x * blockDim.x + threadIdx.x;
    if (i >= (size_t)BB * CC * DD) return;
    int d = (int)(i & (DD - 1));
    float x = vf[i];
    g_vfp[i] = pack_bf(x);
    g_vmlup[i] = pack_bf(x * w4mlu[d]);
}

__global__ void prep_rc_cq(const float* __restrict__ vf, const float* __restrict__ qf,
                           const float* __restrict__ w4C, const float* __restrict__ w4Q) {
    int i = blockIdx.x * blockDim.x + threadIdx.x;
    if (i < BB * CC) {
        const float* row = vf + (size_t)i * DD;
        float s = 0.f;
#pragma unroll 4
        for (int d = 0; d < DD; d++) s += row[d] * w4C[d];
        g_rc[i] = s;
    }
    if (i < BB * QQ) {
        const float* row = qf + (size_t)i * DD;
        float s = 0.f;
#pragma unroll 4
        for (int d = 0; d < DD; d++) s += row[d] * w4Q[d];
        g_cq[i] = s;
    }
}

__global__ void zero_k() {
    int i = blockIdx.x * blockDim.x + threadIdx.x;
    if (i < BB * QQ * DD) g_mid[i] = 0.f;
    if (i < BB * QQ) g_colsum[i] = 0.f;
}

__global__ void pack_mid() {
    int i = blockIdx.x * blockDim.x + threadIdx.x;
    if (i >= BB * QQ * DD) return;
    int q = (i >> 7) & (QQ - 1);
    int b = i >> 14;
    g_midp[i] = pack_bf(g_mid[i] * (1.f / g_colsum[b * QQ + q]));
}

// ----------------------------------------------------------------------------
// Pooled query projection
// ----------------------------------------------------------------------------
__global__ void pooled_kernel(const float* __restrict__ qf, const float* __restrict__ qmask,
                              const float* __restrict__ wp, const float* __restrict__ cc_W,
                              const float* __restrict__ cc_b) {
    __shared__ float sred[QQ];
    __shared__ float s_al[QQ];
    __shared__ float s_pool[DD];
    int b = blockIdx.x, t = threadIdx.x;

    const float* row = qf + (size_t)(b * QQ + t) * DD;
    float x = 0.f;
#pragma unroll 4
    for (int d = 0; d < DD; d++) x += row[d] * wp[d];
    x += (1.f - qmask[b * QQ + t]) * MASKV;

    sred[t] = x; __syncthreads();
    for (int s = 64; s > 0; s >>= 1) {
        if (t < s) sred[t] = fmaxf(sred[t], sred[t + s]);
        __syncthreads();
    }
    float m = sred[0]; __syncthreads();
    float e = __expf(x - m);
    sred[t] = e; __syncthreads();
    for (int s = 64; s > 0; s >>= 1) {
        if (t < s) sred[t] += sred[t + s];
        __syncthreads();
    }
    float inv = 1.f / sred[0];
    s_al[t] = e * inv; __syncthreads();

    float p = 0.f;
#pragma unroll 4
    for (int q = 0; q < QQ; q++) p += s_al[q] * qf[(size_t)(b * QQ + q) * DD + t];
    s_pool[t] = p; __syncthreads();

    float o = cc_b[t];
#pragma unroll 4
    for (int k = 0; k < DD; k++) o += s_pool[k] * cc_W[t * (2 * DD) + DD + k];
    g_pproj[b * DD + t] = o;
}

// ----------------------------------------------------------------------------
// Score kernel: E = exp(score), + masked column sums
// ----------------------------------------------------------------------------
__global__ __launch_bounds__(256) void score_kernel(const float* __restrict__ vmask) {
    extern __shared__ unsigned su[];
    unsigned* sAp = su;               // [64][SA]
    unsigned* sBp = su + CT * SA;     // [128][SB]

    int b = blockIdx.y, c0 = blockIdx.x * CT, tid = threadIdx.x;

    {
        const uint4* srcA = (const uint4*)(g_vmlup + (size_t)(b * CC + c0) * DD);
        for (int i = tid; i < CT * DD / 4; i += 256)
            *(uint4*)&sAp[(i >> 5) * SA + (i & 31) * 4] = srcA[i];
        const uint4* srcB = (const uint4*)(g_qfTp + (size_t)b * DD * QQ);
        for (int i = tid; i < DD * QQ / 4; i += 256)
            *(uint4*)&sBp[(i >> 5) * SB + (i & 31) * 4] = srcB[i];
    }
    __syncthreads();

    int warp = tid >> 5, lane = tid & 31;
    int gr = lane >> 2, tg = lane & 3;
    int wr0 = (warp & 1) * 32, wc0 = (warp >> 1) * 32;

    float acc[2][4][4];
#pragma unroll
    for (int rb = 0; rb < 2; rb++)
#pragma unroll
        for (int nt = 0; nt < 4; nt++)
#pragma unroll
            for (int j = 0; j < 4; j++) acc[rb][nt][j] = 0.f;

    mma_stage_p<4, SA, SB, 128>(sAp, sBp, acc, wr0, wc0, lane);

    float vm[4];
    vm[0] = vmask[b * CC + c0 + wr0 + gr];
    vm[1] = vmask[b * CC + c0 + wr0 + gr + 8];
    vm[2] = vmask[b * CC + c0 + wr0 + gr + 16];
    vm[3] = vmask[b * CC + c0 + wr0 + gr + 24];

#pragma unroll
    for (int rb = 0; rb < 2; rb++) {
        int r = wr0 + rb * 16 + gr;
        float rc0 = g_rc[b * CC + c0 + r];
        float rc1 = g_rc[b * CC + c0 + r + 8];
#pragma unroll
        for (int nt = 0; nt < 4; nt++) {
            int q = wc0 + nt * 8 + 2 * tg;
            float cq0 = g_cq[b * QQ + q], cq1 = g_cq[b * QQ + q + 1];
            acc[rb][nt][0] = __expf(acc[rb][nt][0] + rc0 + cq0);
            acc[rb][nt][1] = __expf(acc[rb][nt][1] + rc0 + cq1);
            acc[rb][nt][2] = __expf(acc[rb][nt][2] + rc1 + cq0);
            acc[rb][nt][3] = __expf(acc[rb][nt][3] + rc1 + cq1);
            float* d0 = g_score + ((size_t)(b * CC + c0 + r)) * QQ + q;
            float* d1 = g_score + ((size_t)(b * CC + c0 + r + 8)) * QQ + q;
            *(float2*)d0 = make_float2(acc[rb][nt][0], acc[rb][nt][1]);
            *(float2*)d1 = make_float2(acc[rb][nt][2], acc[rb][nt][3]);
        }
    }

#pragma unroll
    for (int nt = 0; nt < 4; nt++) {
#pragma unroll
        for (int j = 0; j < 2; j++) {
            float cs = acc[0][nt][j] * vm[0] + acc[0][nt][j + 2] * vm[1] +
                       acc[1][nt][j] * vm[2] + acc[1][nt][j + 2] * vm[3];
            cs += __shfl_xor_sync(0xffffffffu, cs, 4);
            cs += __shfl_xor_sync(0xffffffffu, cs, 8);
            cs += __shfl_xor_sync(0xffffffffu, cs, 16);
            if (lane < 4)
                atomicAdd(&g_colsum[b * QQ + wc0 + nt * 8 + 2 * tg + j], cs);
        }
    }
}

// ----------------------------------------------------------------------------
// mid(unscaled)[q,d] = sum_c E[c,q]*vmask[c]*v[c,d]
// ----------------------------------------------------------------------------
__global__ __launch_bounds__(256) void mid_kernel(const float* __restrict__ vmask) {
    __shared__ unsigned u_stT[QQ * SMA];   // [q][kc]
    __shared__ unsigned u_v[16 * SB];      // [kc][d]
    int b = blockIdx.x, sp = blockIdx.y, tid = threadIdx.x;
    int cbase = sp * (CC / NSPLIT);
    int warp = tid >> 5, lane = tid & 31;
    int gr = lane >> 2, tg = lane & 3;
    int wr0 = (warp & 3) * 32, wc0 = (warp >> 2) * 64;

    float acc[2][8][4];
#pragma unroll
    for (int rb = 0; rb < 2; rb++)
#pragma unroll
        for (int nt = 0; nt < 8; nt++)
#pragma unroll
            for (int j = 0; j < 4; j++) acc[rb][nt][j] = 0.f;

    for (int cc0 = 0; cc0 < CC / NSPLIT; cc0 += 16) {
        __syncthreads();
        for (int i = tid; i < 16 * QQ; i += 256) {
            int kc = i >> 7, col = i & 127;
            int c = cbase + cc0 + kc;
            float e = g_score[((size_t)(b * CC + c)) * QQ + col] * vmask[b * CC + c];
            u_stT[col * SMA + kc] = pack_bf(e);
        }
        const uint4* sv = (const uint4*)(g_vfp + (size_t)(b * CC + cbase + cc0) * DD);
        for (int i = tid; i < 16 * DD / 4; i += 256)
            *(uint4*)&u_v[(i >> 5) * SB + (i & 31) * 4] = sv[i];
        __syncthreads();
        mma_stage_p<8, SMA, SB, 16>(u_stT, u_v, acc, wr0, wc0, lane);
    }

#pragma unroll
    for (int rb = 0; rb < 2; rb++) {
        int q = wr0 + rb * 16 + gr;
#pragma unroll
        for (int nt = 0; nt < 8; nt++) {
            int d = wc0 + nt * 8 + 2 * tg;
            atomicAdd(&g_mid[(size_t)(b * QQ + q) * DD + d],     acc[rb][nt][0]);
            atomicAdd(&g_mid[(size_t)(b * QQ + q) * DD + d + 1], acc[rb][nt][1]);
            atomicAdd(&g_mid[(size_t)(b * QQ + q + 8) * DD + d],     acc[rb][nt][2]);
            atomicAdd(&g_mid[(size_t)(b * QQ + q + 8) * DD + d + 1], acc[rb][nt][3]);
        }
    }
}

// ----------------------------------------------------------------------------
// Mega-fused pipeline
// ----------------------------------------------------------------------------
__global__ __launch_bounds__(256, 1) void fused_kernel(const float* __restrict__ vf,
                                                       const float* __restrict__ qmask,
                                                       const float* __restrict__ cqa_b,
                                                       float* __restrict__ out) {
    extern __shared__ char smc[];
    unsigned* u_A   = (unsigned*)smc;                       // [64][SA]
    unsigned* u_B   = u_A + CT * SA;                        // [128][SB]
    float*    f_v   = (float*)(u_B + DD * SB);              // [64][128]
    float*    f_c2q = f_v + CT * DD;                        // [64][128]
    float*    f_q2c = f_c2q + CT * DD;                      // [64][128]

    int b = blockIdx.y;
    int c0 = blockIdx.x * CT;
    int tid = threadIdx.x;
    int warp = tid >> 5, lane = tid & 31;
    int gr = lane >> 2, tg = lane & 3;
    int wr0 = (warp & 1) * 32, wc0 = (warp >> 1) * 32;

    // Phase 0: row softmax from E (no exp) -> packed A; fill f_v; fill B=qf
    {
        float qm[4];
#pragma unroll
        for (int j = 0; j < 4; j++) qm[j] = qmask[b * QQ + lane + 32 * j];
#pragma unroll
        for (int rr = 0; rr < 8; rr++) {
            int r = warp * 8 + rr;
            const float* src = g_score + ((size_t)(b * CC + c0 + r)) * QQ;
            float em[4];
            float s = 0.f;
#pragma unroll
            for (int j = 0; j < 4; j++) { em[j] = src[lane + 32 * j] * qm[j]; s += em[j]; }
#pragma unroll
            for (int off = 16; off > 0; off >>= 1)
                s += __shfl_xor_sync(0xffffffffu, s, off);
            float inv = 1.f / s;
#pragma unroll
            for (int j = 0; j < 4; j++)
                u_A[r * SA + lane + 32 * j] = pack_bf(em[j] * inv);
        }
        const float4* src = (const float4*)(vf + ((size_t)(b * CC + c0)) * DD);
        float4* dst = (float4*)f_v;
        for (int i = tid; i < CT * DD / 4; i += 256) dst[i] = src[i];
        const uint4* qs = (const uint4*)(g_qfp + (size_t)b * QQ * DD);
        for (int i = tid; i < QQ * DD / 4; i += 256)
            *(uint4*)&u_B[(i >> 5) * SB + (i & 31) * 4] = qs[i];
    }
    __syncthreads();

    float acc[2][4][4];
#define ZERO_ACC(A_)                                      \
    _Pragma("unroll") for (int rb = 0; rb < 2; rb++)      \
    _Pragma("unroll") for (int nt = 0; nt < 4; nt++)      \
    _Pragma("unroll") for (int j = 0; j < 4; j++) A_[rb][nt][j] = 0.f;

#define STORE_F32(DST, A_)                                                      \
    _Pragma("unroll") for (int rb = 0; rb < 2; rb++) {                          \
        int r_ = wr0 + rb * 16 + gr;                                            \
        _Pragma("unroll") for (int nt = 0; nt < 4; nt++) {                      \
            int cI = wc0 + nt * 8 + 2 * tg;                                     \
            (DST)[r_ * DD + cI]       = A_[rb][nt][0];                          \
            (DST)[r_ * DD + cI + 1]   = A_[rb][nt][1];                          \
            (DST)[(r_ + 8) * DD + cI]     = A_[rb][nt][2];                      \
            (DST)[(r_ + 8) * DD + cI + 1] = A_[rb][nt][3];                      \
        }                                                                       \
    }

#define FILL_B(SRC)                                                             \
    {                                                                           \
        const uint4* s_ = (const uint4*)(SRC);                                  \
        for (int i = tid; i < DD * DD / 4; i += 256)                            \
            *(uint4*)&u_B[(i >> 5) * SB + (i & 31) * 4] = s_[i];                \
    }

    // Stage 1: c2q = sc @ qf
    ZERO_ACC(acc)
    mma_stage_p<4, SA, SB, 128>(u_A, u_B, acc, wr0, wc0, lane);
    STORE_F32(f_c2q, acc)
    __syncthreads();

    // Stage 2: q2c = sc @ midS
    FILL_B(g_midp + (size_t)b * QQ * DD)
    __syncthreads();
    ZERO_ACC(acc)
    mma_stage_p<4, SA, SB, 128>(u_A, u_B, acc, wr0, wc0, lane);
    STORE_F32(f_q2c, acc)
    __syncthreads();

    // Stages 3-6: feats = [v, c2q, v*c2q, v*q2c] @ cqa_W.T + cqa_b
    float facc[2][4][4];
#pragma unroll
    for (int rb = 0; rb < 2; rb++)
#pragma unroll
        for (int nt = 0; nt < 4; nt++) {
            int d = wc0 + nt * 8 + 2 * tg;
            float b0 = cqa_b[d], b1 = cqa_b[d + 1];
            facc[rb][nt][0] = b0; facc[rb][nt][1] = b1;
            facc[rb][nt][2] = b0; facc[rb][nt][3] = b1;
        }

    // part 0: A = v
    for (int i = tid; i < CT * DD; i += 256)
        u_A[(i >> 7) * SA + (i & 127)] = pack_bf(f_v[i]);
    FILL_B(g_cqaWTp)
    __syncthreads();
    mma_stage_p<4, SA, SB, 128>(u_A, u_B, facc, wr0, wc0, lane);
    __syncthreads();

    // part 1: A = c2q
    for (int i = tid; i < CT * DD; i += 256)
        u_A[(i >> 7) * SA + (i & 127)] = pack_bf(f_c2q[i]);
    FILL_B(g_cqaWTp + DD * DD)
    __syncthreads();
    mma_stage_p<4, SA, SB, 128>(u_A, u_B, facc, wr0, wc0, lane);
    __syncthreads();

    // part 2: A = v*c2q
    for (int i = tid; i < CT * DD; i += 256)
        u_A[(i >> 7) * SA + (i & 127)] = pack_bf(f_v[i] * f_c2q[i]);
    FILL_B(g_cqaWTp + 2 * DD * DD)
    __syncthreads();
    mma_stage_p<4, SA, SB, 128>(u_A, u_B, facc, wr0, wc0, lane);
    __syncthreads();

    // part 3: A = v*q2c
    for (int i = tid; i < CT * DD; i += 256)
        u_A[(i >> 7) * SA + (i & 127)] = pack_bf(f_v[i] * f_q2c[i]);
    FILL_B(g_cqaWTp + 3 * DD * DD)
    __syncthreads();
    mma_stage_p<4, SA, SB, 128>(u_A, u_B, facc, wr0, wc0, lane);
    __syncthreads();

    // Stage 7: out = relu(feats @ ccW + pproj); feats packed from regs
#pragma unroll
    for (int rb = 0; rb < 2; rb++) {
        int r = wr0 + rb * 16 + gr;
#pragma unroll
        for (int nt = 0; nt < 4; nt++) {
            int cI = wc0 + nt * 8 + 2 * tg;
            u_A[r * SA + cI]       = pack_bf(facc[rb][nt][0]);
            u_A[r * SA + cI + 1]   = pack_bf(facc[rb][nt][1]);
            u_A[(r + 8) * SA + cI]     = pack_bf(facc[rb][nt][2]);
            u_A[(r + 8) * SA + cI + 1] = pack_bf(facc[rb][nt][3]);
        }
    }
    FILL_B(g_ccWTp)
    __syncthreads();

    float oacc[2][4][4];
#pragma unroll
    for (int rb = 0; rb < 2; rb++)
#pragma unroll
        for (int nt = 0; nt < 4; nt++) {
            int d = wc0 + nt * 8 + 2 * tg;
            float p0 = g_pproj[b * DD + d], p1 = g_pproj[b * DD + d + 1];
            oacc[rb][nt][0] = p0; oacc[rb][nt][1] = p1;
            oacc[rb][nt][2] = p0; oacc[rb][nt][3] = p1;
        }
    mma_stage_p<4, SA, SB, 128>(u_A, u_B, oacc, wr0, wc0, lane);

#pragma unroll
    for (int rb = 0; rb < 2; rb++) {
        int r = wr0 + rb * 16 + gr;
#pragma unroll
        for (int nt = 0; nt < 4; nt++) {
            int d = wc0 + nt * 8 + 2 * tg;
            float* d0 = out + ((size_t)(b * CC + c0 + r)) * DD + d;
            float* d1 = out + ((size_t)(b * CC + c0 + r + 8)) * DD + d;
            *(float2*)d0 = make_float2(fmaxf(oacc[rb][nt][0], 0.f), fmaxf(oacc[rb][nt][1], 0.f));
            *(float2*)d1 = make_float2(fmaxf(oacc[rb][nt][2], 0.f), fmaxf(oacc[rb][nt][3], 0.f));
        }
    }
}

// ----------------------------------------------------------------------------
// Launch
// ----------------------------------------------------------------------------
extern "C" void kernel_launch(void* const* d_in, const int* in_sizes, int n_in,
                              void* d_out, int out_size) {
    const float* vfeats = (const float*)d_in[0];
    const float* qfeats = (const float*)d_in[1];
    const float* vmask  = (const float*)d_in[2];
    const float* qmask  = (const float*)d_in[3];
    const float* w4C    = (const float*)d_in[4];
    const float* w4Q    = (const float*)d_in[5];
    const float* w4mlu  = (const float*)d_in[6];
    const float* cqa_W  = (const float*)d_in[7];
    const float* cqa_b  = (const float*)d_in[8];
    const float* wp     = (const float*)d_in[9];
    const float* cc_W   = (const float*)d_in[10];
    const float* cc_b   = (const float*)d_in[11];
    float* out = (float*)d_out;

    const int SCORE_SMEM = (CT * SA + DD * SB) * (int)sizeof(unsigned);            // ~101 KB
    const int FUSED_SMEM = (CT * SA + DD * SB) * 4 + 3 * CT * DD * 4;              // ~200 KB
    cudaFuncSetAttribute(score_kernel, cudaFuncAttributeMaxDynamicSharedMemorySize, SCORE_SMEM);
    cudaFuncSetAttribute(fused_kernel, cudaFuncAttributeMaxDynamicSharedMemorySize, FUSED_SMEM);

    prep_w<<<(4 * DD * DD + 255) / 256, 256>>>(cqa_W, cc_W);
    prep_qf<<<(BB * DD * QQ + 255) / 256, 256>>>(qfeats);
    prep_vf<<<(int)(((size_t)BB * CC * DD + 255) / 256), 256>>>(vfeats, w4mlu);
    prep_rc_cq<<<(BB * CC + 255) / 256, 256>>>(vfeats, qfeats, w4C, w4Q);
    zero_k<<<(BB * QQ * DD + 255) / 256, 256>>>();
    pooled_kernel<<<BB, QQ>>>(qfeats, qmask, wp, cc_W, cc_b);
    score_kernel<<<dim3(CC / CT, BB), 256, SCORE_SMEM>>>(vmask);
    mid_kernel<<<dim3(BB, NSPLIT), 256>>>(vmask);
    pack_mid<<<(BB * QQ * DD + 255) / 256, 256>>>();
    fused_kernel<<<dim3(CC / CT, BB), 256, FUSED_SMEM>>>(vfeats, qmask, cqa_b, out);
}

// round 10
// speedup vs baseline: 1.3030x; 1.1383x over previous
#include <cuda_runtime.h>
#include <cuda_bf16.h>
#include <math.h>

#define BB 64
#define CC 2048
#define QQ 128
#define DD 128
#define CT 64
#define NSPLIT 4
#define MASKV (-1e30f)
#define SA 132    // packed A-tile word stride
#define SB 136    // packed B-tile word stride
#define SMA 18    // mid stT word stride

// ----------------------------------------------------------------------------
// Device scratch
// ----------------------------------------------------------------------------
__device__ float    g_score[(size_t)BB * CC * QQ];  // E = exp(raw score)
__device__ float    g_rc[BB * CC];
__device__ float    g_cq[BB * QQ];
__device__ float    g_colsum[BB * QQ];
__device__ float    g_mid[BB * QQ * DD];
__device__ float    g_pproj[BB * DD];               // pooled proj + cqa_b@ccW1.T + cc_b
__device__ unsigned g_midp[BB * QQ * DD];           // packed (mid/colsum)
__device__ unsigned g_qfTp[BB * DD * QQ];           // packed qfeats^T [b][d][q]
__device__ unsigned g_qfp[BB * QQ * DD];            // packed qfeats  [b][q][d]
__device__ unsigned g_vfp[(size_t)BB * CC * DD];    // packed vfeats
__device__ unsigned g_vmlup[(size_t)BB * CC * DD];  // packed vfeats*w4mlu
__device__ unsigned g_GWp[4 * DD * DD];             // packed G=ccW1@cqa_W: [part][k][d]

// ----------------------------------------------------------------------------
// bf16-split helpers
// ----------------------------------------------------------------------------
__device__ __forceinline__ unsigned pack_bf(float x) {
    unsigned h = (unsigned)__bfloat16_as_ushort(__float2bfloat16(x));
    float hf = __uint_as_float(h << 16);
    unsigned l = (unsigned)__bfloat16_as_ushort(__float2bfloat16(x - hf));
    return h | (l << 16);
}

__device__ __forceinline__ float unpack_bf(unsigned w) {
    return __uint_as_float(w << 16) + __uint_as_float(w & 0xffff0000u);
}

__device__ __forceinline__ void mma_bf16(float c[4], const unsigned a[4], const unsigned b[2]) {
    asm volatile(
        "mma.sync.aligned.m16n8k16.row.col.f32.bf16.bf16.f32 "
        "{%0,%1,%2,%3}, {%4,%5,%6,%7}, {%8,%9}, {%0,%1,%2,%3};"
        : "+f"(c[0]), "+f"(c[1]), "+f"(c[2]), "+f"(c[3])
        : "r"(a[0]), "r"(a[1]), "r"(a[2]), "r"(a[3]), "r"(b[0]), "r"(b[1]));
}

// Warp computes C[wr0:wr0+32][wc0:wc0+NT*8] += A @ B from packed smem.
template <int NT, int SAs, int SBs, int K>
__device__ __forceinline__ void mma_stage_p(const unsigned* __restrict__ A,
                                            const unsigned* __restrict__ B,
                                            float acc[2][NT][4],
                                            int wr0, int wc0, int lane) {
    const int gr = lane >> 2, t2 = (lane & 3) * 2;
#pragma unroll
    for (int k0 = 0; k0 < K; k0 += 16) {
        unsigned ah[2][4], al[2][4];
#pragma unroll
        for (int rb = 0; rb < 2; rb++) {
            const unsigned* p0 = A + (wr0 + rb * 16 + gr) * SAs + k0 + t2;
            const unsigned* p1 = A + (wr0 + rb * 16 + 8 + gr) * SAs + k0 + t2;
            uint2 wa = *(const uint2*)p0;
            uint2 wb = *(const uint2*)p1;
            uint2 wc = *(const uint2*)(p0 + 8);
            uint2 wd = *(const uint2*)(p1 + 8);
            ah[rb][0] = __byte_perm(wa.x, wa.y, 0x5410); al[rb][0] = __byte_perm(wa.x, wa.y, 0x7632);
            ah[rb][1] = __byte_perm(wb.x, wb.y, 0x5410); al[rb][1] = __byte_perm(wb.x, wb.y, 0x7632);
            ah[rb][2] = __byte_perm(wc.x, wc.y, 0x5410); al[rb][2] = __byte_perm(wc.x, wc.y, 0x7632);
            ah[rb][3] = __byte_perm(wd.x, wd.y, 0x5410); al[rb][3] = __byte_perm(wd.x, wd.y, 0x7632);
        }
#pragma unroll
        for (int nt = 0; nt < NT; nt++) {
            int n = wc0 + nt * 8 + gr;
            unsigned v0 = B[(k0 + t2) * SBs + n];
            unsigned v1 = B[(k0 + t2 + 1) * SBs + n];
            unsigned v2 = B[(k0 + 8 + t2) * SBs + n];
            unsigned v3 = B[(k0 + 9 + t2) * SBs + n];
            unsigned bh[2] = {__byte_perm(v0, v1, 0x5410), __byte_perm(v2, v3, 0x5410)};
            unsigned bl[2] = {__byte_perm(v0, v1, 0x7632), __byte_perm(v2, v3, 0x7632)};
#pragma unroll
            for (int rb = 0; rb < 2; rb++) {
                mma_bf16(acc[rb][nt], ah[rb], bh);
                mma_bf16(acc[rb][nt], al[rb], bh);
                mma_bf16(acc[rb][nt], ah[rb], bl);
            }
        }
    }
}

// ----------------------------------------------------------------------------
// Prep kernels
// ----------------------------------------------------------------------------
// G[d, part*DD+k] = sum_j ccW1[d][j] * cqa_W[j][part*DD+k]; packed [col][d]
__global__ void prep_G(const float* __restrict__ cqa_W, const float* __restrict__ cc_W) {
    __shared__ float s_col[DD];
    int col = blockIdx.x;   // 0..4*DD-1
    int d = threadIdx.x;
    s_col[d] = cqa_W[d * (4 * DD) + col];
    __syncthreads();
    float s = 0.f;
#pragma unroll 4
    for (int j = 0; j < DD; j++) s += cc_W[d * (2 * DD) + j] * s_col[j];
    g_GWp[col * DD + d] = pack_bf(s);
}

__global__ void prep_qf(const float* __restrict__ qf) {
    int i = blockIdx.x * blockDim.x + threadIdx.x;
    if (i >= BB * DD * QQ) return;
    int q = i % QQ;
    int t = i / QQ;
    int d = t % DD;
    int b = t / DD;
    g_qfTp[i] = pack_bf(qf[((size_t)(b * QQ + q)) * DD + d]);
    g_qfp[i] = pack_bf(qf[i]);
}

__global__ void prep_vf(const float* __restrict__ vf, const float* __restrict__ w4mlu) {
    size_t i = (size_t)blockIdx.x * blockDim.x + threadIdx.x;
    if (i >= (size_t)BB * CC * DD) return;
    int d = (int)(i & (DD - 1));
    float x = vf[i];
    g_vfp[i] = pack_bf(x);
    g_vmlup[i] = pack_bf(x * w4mlu[d]);
}

// warp-per-row coalesced dot products
__global__ void prep_rc(const float* __restrict__ vf, const float* __restrict__ w4C) {
    int row = blockIdx.x * 8 + (threadIdx.x >> 5);
    int lane = threadIdx.x & 31;
    float4 t = *(const float4*)(vf + (size_t)row * DD + lane * 4);
    float4 w = *(const float4*)(w4C + lane * 4);
    float s = t.x * w.x + t.y * w.y + t.z * w.z + t.w * w.w;
#pragma unroll
    for (int off = 16; off > 0; off >>= 1) s += __shfl_xor_sync(0xffffffffu, s, off);
    if (lane == 0) g_rc[row] = s;
}

__global__ void prep_cq(const float* __restrict__ qf, const float* __restrict__ w4Q) {
    int row = blockIdx.x * 8 + (threadIdx.x >> 5);
    int lane = threadIdx.x & 31;
    float4 t = *(const float4*)(qf + (size_t)row * DD + lane * 4);
    float4 w = *(const float4*)(w4Q + lane * 4);
    float s = t.x * w.x + t.y * w.y + t.z * w.z + t.w * w.w;
#pragma unroll
    for (int off = 16; off > 0; off >>= 1) s += __shfl_xor_sync(0xffffffffu, s, off);
    if (lane == 0) g_cq[row] = s;
}

__global__ void zero_k() {
    int i = blockIdx.x * blockDim.x + threadIdx.x;
    if (i < BB * QQ * DD) g_mid[i] = 0.f;
    if (i < BB * QQ) g_colsum[i] = 0.f;
}

__global__ void pack_mid() {
    int i = blockIdx.x * blockDim.x + threadIdx.x;
    if (i >= BB * QQ * DD) return;
    int q = (i >> 7) & (QQ - 1);
    int b = i >> 14;
    g_midp[i] = pack_bf(g_mid[i] * (1.f / g_colsum[b * QQ + q]));
}

// ----------------------------------------------------------------------------
// Pooled projection (+ folded cqa_b @ ccW1.T + cc_b)
// ----------------------------------------------------------------------------
__global__ void pooled_kernel(const float* __restrict__ qf, const float* __restrict__ qmask,
                              const float* __restrict__ wp, const float* __restrict__ cc_W,
                              const float* __restrict__ cc_b, const float* __restrict__ cqa_b) {
    __shared__ float sred[QQ];
    __shared__ float s_al[QQ];
    __shared__ float s_pool[DD];
    int b = blockIdx.x, t = threadIdx.x;

    const float* row = qf + (size_t)(b * QQ + t) * DD;
    float x = 0.f;
#pragma unroll 4
    for (int d = 0; d < DD; d++) x += row[d] * wp[d];
    x += (1.f - qmask[b * QQ + t]) * MASKV;

    sred[t] = x; __syncthreads();
    for (int s = 64; s > 0; s >>= 1) {
        if (t < s) sred[t] = fmaxf(sred[t], sred[t + s]);
        __syncthreads();
    }
    float m = sred[0]; __syncthreads();
    float e = __expf(x - m);
    sred[t] = e; __syncthreads();
    for (int s = 64; s > 0; s >>= 1) {
        if (t < s) sred[t] += sred[t + s];
        __syncthreads();
    }
    float inv = 1.f / sred[0];
    s_al[t] = e * inv; __syncthreads();

    float p = 0.f;
#pragma unroll 4
    for (int q = 0; q < QQ; q++) p += s_al[q] * qf[(size_t)(b * QQ + q) * DD + t];
    s_pool[t] = p; __syncthreads();

    float o = cc_b[t];
#pragma unroll 4
    for (int k = 0; k < DD; k++) {
        o += s_pool[k] * cc_W[t * (2 * DD) + DD + k];   // pooled part
        o += cqa_b[k] * cc_W[t * (2 * DD) + k];         // folded cqa bias
    }
    g_pproj[b * DD + t] = o;
}

// ----------------------------------------------------------------------------
// Score kernel: E = exp(score), + masked column sums
// ----------------------------------------------------------------------------
__global__ __launch_bounds__(256) void score_kernel(const float* __restrict__ vmask) {
    extern __shared__ unsigned su[];
    unsigned* sAp = su;               // [64][SA]
    unsigned* sBp = su + CT * SA;     // [128][SB]

    int b = blockIdx.y, c0 = blockIdx.x * CT, tid = threadIdx.x;

    {
        const uint4* srcA = (const uint4*)(g_vmlup + (size_t)(b * CC + c0) * DD);
        for (int i = tid; i < CT * DD / 4; i += 256)
            *(uint4*)&sAp[(i >> 5) * SA + (i & 31) * 4] = srcA[i];
        const uint4* srcB = (const uint4*)(g_qfTp + (size_t)b * DD * QQ);
        for (int i = tid; i < DD * QQ / 4; i += 256)
            *(uint4*)&sBp[(i >> 5) * SB + (i & 31) * 4] = srcB[i];
    }
    __syncthreads();

    int warp = tid >> 5, lane = tid & 31;
    int gr = lane >> 2, tg = lane & 3;
    int wr0 = (warp & 1) * 32, wc0 = (warp >> 1) * 32;

    float acc[2][4][4];
#pragma unroll
    for (int rb = 0; rb < 2; rb++)
#pragma unroll
        for (int nt = 0; nt < 4; nt++)
#pragma unroll
            for (int j = 0; j < 4; j++) acc[rb][nt][j] = 0.f;

    mma_stage_p<4, SA, SB, 128>(sAp, sBp, acc, wr0, wc0, lane);

    float vm[4];
    vm[0] = vmask[b * CC + c0 + wr0 + gr];
    vm[1] = vmask[b * CC + c0 + wr0 + gr + 8];
    vm[2] = vmask[b * CC + c0 + wr0 + gr + 16];
    vm[3] = vmask[b * CC + c0 + wr0 + gr + 24];

#pragma unroll
    for (int rb = 0; rb < 2; rb++) {
        int r = wr0 + rb * 16 + gr;
        float rc0 = g_rc[b * CC + c0 + r];
        float rc1 = g_rc[b * CC + c0 + r + 8];
#pragma unroll
        for (int nt = 0; nt < 4; nt++) {
            int q = wc0 + nt * 8 + 2 * tg;
            float cq0 = g_cq[b * QQ + q], cq1 = g_cq[b * QQ + q + 1];
            acc[rb][nt][0] = __expf(acc[rb][nt][0] + rc0 + cq0);
            acc[rb][nt][1] = __expf(acc[rb][nt][1] + rc0 + cq1);
            acc[rb][nt][2] = __expf(acc[rb][nt][2] + rc1 + cq0);
            acc[rb][nt][3] = __expf(acc[rb][nt][3] + rc1 + cq1);
            float* d0 = g_score + ((size_t)(b * CC + c0 + r)) * QQ + q;
            float* d1 = g_score + ((size_t)(b * CC + c0 + r + 8)) * QQ + q;
            *(float2*)d0 = make_float2(acc[rb][nt][0], acc[rb][nt][1]);
            *(float2*)d1 = make_float2(acc[rb][nt][2], acc[rb][nt][3]);
        }
    }

#pragma unroll
    for (int nt = 0; nt < 4; nt++) {
#pragma unroll
        for (int j = 0; j < 2; j++) {
            float cs = acc[0][nt][j] * vm[0] + acc[0][nt][j + 2] * vm[1] +
                       acc[1][nt][j] * vm[2] + acc[1][nt][j + 2] * vm[3];
            cs += __shfl_xor_sync(0xffffffffu, cs, 4);
            cs += __shfl_xor_sync(0xffffffffu, cs, 8);
            cs += __shfl_xor_sync(0xffffffffu, cs, 16);
            if (lane < 4)
                atomicAdd(&g_colsum[b * QQ + wc0 + nt * 8 + 2 * tg + j], cs);
        }
    }
}

// ----------------------------------------------------------------------------
// mid(unscaled)[q,d] = sum_c E[c,q]*vmask[c]*v[c,d]
// ----------------------------------------------------------------------------
__global__ __launch_bounds__(256) void mid_kernel(const float* __restrict__ vmask) {
    __shared__ unsigned u_stT[QQ * SMA];
    __shared__ unsigned u_v[16 * SB];
    int b = blockIdx.x, sp = blockIdx.y, tid = threadIdx.x;
    int cbase = sp * (CC / NSPLIT);
    int warp = tid >> 5, lane = tid & 31;
    int gr = lane >> 2, tg = lane & 3;
    int wr0 = (warp & 3) * 32, wc0 = (warp >> 2) * 64;

    float acc[2][8][4];
#pragma unroll
    for (int rb = 0; rb < 2; rb++)
#pragma unroll
        for (int nt = 0; nt < 8; nt++)
#pragma unroll
            for (int j = 0; j < 4; j++) acc[rb][nt][j] = 0.f;

    for (int cc0 = 0; cc0 < CC / NSPLIT; cc0 += 16) {
        __syncthreads();
        for (int i = tid; i < 16 * QQ; i += 256) {
            int kc = i >> 7, col = i & 127;
            int c = cbase + cc0 + kc;
            float e = g_score[((size_t)(b * CC + c)) * QQ + col] * vmask[b * CC + c];
            u_stT[col * SMA + kc] = pack_bf(e);
        }
        const uint4* sv = (const uint4*)(g_vfp + (size_t)(b * CC + cbase + cc0) * DD);
        for (int i = tid; i < 16 * DD / 4; i += 256)
            *(uint4*)&u_v[(i >> 5) * SB + (i & 31) * 4] = sv[i];
        __syncthreads();
        mma_stage_p<8, SMA, SB, 16>(u_stT, u_v, acc, wr0, wc0, lane);
    }

#pragma unroll
    for (int rb = 0; rb < 2; rb++) {
        int q = wr0 + rb * 16 + gr;
#pragma unroll
        for (int nt = 0; nt < 8; nt++) {
            int d = wc0 + nt * 8 + 2 * tg;
            atomicAdd(&g_mid[(size_t)(b * QQ + q) * DD + d],     acc[rb][nt][0]);
            atomicAdd(&g_mid[(size_t)(b * QQ + q) * DD + d + 1], acc[rb][nt][1]);
            atomicAdd(&g_mid[(size_t)(b * QQ + q + 8) * DD + d],     acc[rb][nt][2]);
            atomicAdd(&g_mid[(size_t)(b * QQ + q + 8) * DD + d + 1], acc[rb][nt][3]);
        }
    }
}

// ----------------------------------------------------------------------------
// Mega-fused v2: 6 GEMM stages, A-tiles packed, accumulators -> packed direct
// ----------------------------------------------------------------------------
__global__ __launch_bounds__(256, 1) void fused_kernel(const float* __restrict__ qmask,
                                                       float* __restrict__ out) {
    extern __shared__ unsigned su[];
    unsigned* u_sc  = su;                 // [64][SA] sc, later products
    unsigned* u_v   = u_sc + CT * SA;     // [64][SA]
    unsigned* u_c2q = u_v + CT * SA;      // [64][SA]
    unsigned* u_q2c = u_c2q + CT * SA;    // [64][SA]
    unsigned* u_B   = u_q2c + CT * SA;    // [128][SB]

    int b = blockIdx.y;
    int c0 = blockIdx.x * CT;
    int tid = threadIdx.x;
    int warp = tid >> 5, lane = tid & 31;
    int gr = lane >> 2, tg = lane & 3;
    int wr0 = (warp & 1) * 32, wc0 = (warp >> 1) * 32;

    // Phase 0: row softmax from E -> packed u_sc; u_v from g_vfp; u_B = qfp
    {
        float qm[4];
#pragma unroll
        for (int j = 0; j < 4; j++) qm[j] = qmask[b * QQ + lane + 32 * j];
#pragma unroll
        for (int rr = 0; rr < 8; rr++) {
            int r = warp * 8 + rr;
            const float* src = g_score + ((size_t)(b * CC + c0 + r)) * QQ;
            float em[4];
            float s = 0.f;
#pragma unroll
            for (int j = 0; j < 4; j++) { em[j] = src[lane + 32 * j] * qm[j]; s += em[j]; }
#pragma unroll
            for (int off = 16; off > 0; off >>= 1)
                s += __shfl_xor_sync(0xffffffffu, s, off);
            float inv = 1.f / s;
#pragma unroll
            for (int j = 0; j < 4; j++)
                u_sc[r * SA + lane + 32 * j] = pack_bf(em[j] * inv);
        }
        const uint4* vs = (const uint4*)(g_vfp + (size_t)(b * CC + c0) * DD);
        for (int i = tid; i < CT * DD / 4; i += 256)
            *(uint4*)&u_v[(i >> 5) * SA + (i & 31) * 4] = vs[i];
        const uint4* qs = (const uint4*)(g_qfp + (size_t)b * QQ * DD);
        for (int i = tid; i < QQ * DD / 4; i += 256)
            *(uint4*)&u_B[(i >> 5) * SB + (i & 31) * 4] = qs[i];
    }
    __syncthreads();

#define ZERO_ACC(A_)                                      \
    _Pragma("unroll") for (int rb = 0; rb < 2; rb++)      \
    _Pragma("unroll") for (int nt = 0; nt < 4; nt++)      \
    _Pragma("unroll") for (int j = 0; j < 4; j++) A_[rb][nt][j] = 0.f;

#define PACK_ACC(DST, A_)                                                       \
    _Pragma("unroll") for (int rb = 0; rb < 2; rb++) {                          \
        int r_ = wr0 + rb * 16 + gr;                                            \
        _Pragma("unroll") for (int nt = 0; nt < 4; nt++) {                      \
            int cI = wc0 + nt * 8 + 2 * tg;                                     \
            (DST)[r_ * SA + cI]           = pack_bf(A_[rb][nt][0]);             \
            (DST)[r_ * SA + cI + 1]       = pack_bf(A_[rb][nt][1]);             \
            (DST)[(r_ + 8) * SA + cI]     = pack_bf(A_[rb][nt][2]);             \
            (DST)[(r_ + 8) * SA + cI + 1] = pack_bf(A_[rb][nt][3]);             \
        }                                                                       \
    }

#define FILL_B(SRC)                                                             \
    {                                                                           \
        const uint4* s_ = (const uint4*)(SRC);                                  \
        for (int i = tid; i < DD * DD / 4; i += 256)                            \
            *(uint4*)&u_B[(i >> 5) * SB + (i & 31) * 4] = s_[i];                \
    }

#define PROD_PASS(DST, X, Y)                                                    \
    for (int i = tid; i < CT * DD; i += 256) {                                  \
        int a_ = (i >> 7) * SA + (i & 127);                                     \
        (DST)[a_] = pack_bf(unpack_bf((X)[a_]) * unpack_bf((Y)[a_]));           \
    }

    float acc[2][4][4], oacc[2][4][4];

    // S1: c2q = sc @ qf  -> packed u_c2q (from regs)
    ZERO_ACC(acc)
    mma_stage_p<4, SA, SB, 128>(u_sc, u_B, acc, wr0, wc0, lane);
    PACK_ACC(u_c2q, acc)
    __syncthreads();

    // S2: q2c = sc @ midS -> packed u_q2c
    FILL_B(g_midp + (size_t)b * QQ * DD)
    __syncthreads();
    ZERO_ACC(acc)
    mma_stage_p<4, SA, SB, 128>(u_sc, u_B, acc, wr0, wc0, lane);
    PACK_ACC(u_q2c, acc)
    __syncthreads();

    // S3: oacc = pproj' + v @ G0
#pragma unroll
    for (int rb = 0; rb < 2; rb++)
#pragma unroll
        for (int nt = 0; nt < 4; nt++) {
            int d = wc0 + nt * 8 + 2 * tg;
            float p0 = g_pproj[b * DD + d], p1 = g_pproj[b * DD + d + 1];
            oacc[rb][nt][0] = p0; oacc[rb][nt][1] = p1;
            oacc[rb][nt][2] = p0; oacc[rb][nt][3] = p1;
        }
    FILL_B(g_GWp)
    __syncthreads();
    mma_stage_p<4, SA, SB, 128>(u_v, u_B, oacc, wr0, wc0, lane);
    __syncthreads();

    // S4: += c2q @ G1
    FILL_B(g_GWp + DD * DD)
    __syncthreads();
    mma_stage_p<4, SA, SB, 128>(u_c2q, u_B, oacc, wr0, wc0, lane);
    __syncthreads();

    // S5: += (v*c2q) @ G2   (product into u_sc, sc dead)
    PROD_PASS(u_sc, u_v, u_c2q)
    FILL_B(g_GWp + 2 * DD * DD)
    __syncthreads();
    mma_stage_p<4, SA, SB, 128>(u_sc, u_B, oacc, wr0, wc0, lane);
    __syncthreads();

    // S6: += (v*q2c) @ G3
    PROD_PASS(u_sc, u_v, u_q2c)
    FILL_B(g_GWp + 3 * DD * DD)
    __syncthreads();
    mma_stage_p<4, SA, SB, 128>(u_sc, u_B, oacc, wr0, wc0, lane);

    // epilogue: relu + store
#pragma unroll
    for (int rb = 0; rb < 2; rb++) {
        int r = wr0 + rb * 16 + gr;
#pragma unroll
        for (int nt = 0; nt < 4; nt++) {
            int d = wc0 + nt * 8 + 2 * tg;
            float* d0 = out + ((size_t)(b * CC + c0 + r)) * DD + d;
            float* d1 = out + ((size_t)(b * CC + c0 + r + 8)) * DD + d;
            *(float2*)d0 = make_float2(fmaxf(oacc[rb][nt][0], 0.f), fmaxf(oacc[rb][nt][1], 0.f));
            *(float2*)d1 = make_float2(fmaxf(oacc[rb][nt][2], 0.f), fmaxf(oacc[rb][nt][3], 0.f));
        }
    }
}

// ----------------------------------------------------------------------------
// Launch
// ----------------------------------------------------------------------------
extern "C" void kernel_launch(void* const* d_in, const int* in_sizes, int n_in,
                              void* d_out, int out_size) {
    const float* vfeats = (const float*)d_in[0];
    const float* qfeats = (const float*)d_in[1];
    const float* vmask  = (const float*)d_in[2];
    const float* qmask  = (const float*)d_in[3];
    const float* w4C    = (const float*)d_in[4];
    const float* w4Q    = (const float*)d_in[5];
    const float* w4mlu  = (const float*)d_in[6];
    const float* cqa_W  = (const float*)d_in[7];
    const float* cqa_b  = (const float*)d_in[8];
    const float* wp     = (const float*)d_in[9];
    const float* cc_W   = (const float*)d_in[10];
    const float* cc_b   = (const float*)d_in[11];
    float* out = (float*)d_out;

    const int SCORE_SMEM = (CT * SA + DD * SB) * (int)sizeof(unsigned);       // ~101 KB
    const int FUSED_SMEM = (4 * CT * SA + DD * SB) * (int)sizeof(unsigned);   // ~200 KB
    cudaFuncSetAttribute(score_kernel, cudaFuncAttributeMaxDynamicSharedMemorySize, SCORE_SMEM);
    cudaFuncSetAttribute(fused_kernel, cudaFuncAttributeMaxDynamicSharedMemorySize, FUSED_SMEM);

    prep_G<<<4 * DD, DD>>>(cqa_W, cc_W);
    prep_qf<<<(BB * DD * QQ + 255) / 256, 256>>>(qfeats);
    prep_vf<<<(int)(((size_t)BB * CC * DD + 255) / 256), 256>>>(vfeats, w4mlu);
    prep_rc<<<BB * CC / 8, 256>>>(vfeats, w4C);
    prep_cq<<<BB * QQ / 8, 256>>>(qfeats, w4Q);
    zero_k<<<(BB * QQ * DD + 255) / 256, 256>>>();
    pooled_kernel<<<BB, QQ>>>(qfeats, qmask, wp, cc_W, cc_b, cqa_b);
    score_kernel<<<dim3(CC / CT, BB), 256, SCORE_SMEM>>>(vmask);
    mid_kernel<<<dim3(BB, NSPLIT), 256>>>(vmask);
    pack_mid<<<(BB * QQ * DD + 255) / 256, 256>>>();
    fused_kernel<<<dim3(CC / CT, BB), 256, FUSED_SMEM>>>(qmask, out);
}

// round 13
// speedup vs baseline: 1.8993x; 1.4576x over previous
#include <cuda_runtime.h>
#include <cuda_bf16.h>
#include <math.h>

#define BB 64
#define CC 2048
#define QQ 128
#define DD 128
#define CT 64
#define NSPLIT 4
#define MASKV (-1e30f)
#define SA 132    // packed A-tile word stride
#define SB 136    // packed B-tile word stride
#define SMA 18    // mid stT word stride

// ----------------------------------------------------------------------------
// Device scratch
// ----------------------------------------------------------------------------
__device__ float    g_score[(size_t)BB * CC * QQ];  // E = exp(raw score)
__device__ float    g_rc[BB * CC];
__device__ float    g_cq[BB * QQ];
__device__ float    g_colsum[BB * QQ];
__device__ float    g_mid[BB * QQ * DD];
__device__ float    g_pproj[BB * DD];               // pooled proj + cqa_b@ccW1.T + cc_b
__device__ unsigned g_midp[BB * QQ * DD];           // packed (mid/colsum)
__device__ unsigned g_qfTp[BB * DD * QQ];           // packed qfeats^T [b][d][q]
__device__ unsigned g_qfp[BB * QQ * DD];            // packed qfeats  [b][q][d]
__device__ unsigned g_vfp[(size_t)BB * CC * DD];    // packed vfeats
__device__ unsigned g_vmlup[(size_t)BB * CC * DD];  // packed vfeats*w4mlu
__device__ unsigned g_GWp[4 * DD * DD];             // packed G=ccW1@cqa_W: [part][k][d]

// ----------------------------------------------------------------------------
// bf16-split helpers
// ----------------------------------------------------------------------------
__device__ __forceinline__ unsigned pack_bf(float x) {
    unsigned h = (unsigned)__bfloat16_as_ushort(__float2bfloat16(x));
    float hf = __uint_as_float(h << 16);
    unsigned l = (unsigned)__bfloat16_as_ushort(__float2bfloat16(x - hf));
    return h | (l << 16);
}

__device__ __forceinline__ float unpack_bf(unsigned w) {
    return __uint_as_float(w << 16) + __uint_as_float(w & 0xffff0000u);
}

__device__ __forceinline__ void mma_bf16(float c[4], const unsigned a[4], const unsigned b[2]) {
    asm volatile(
        "mma.sync.aligned.m16n8k16.row.col.f32.bf16.bf16.f32 "
        "{%0,%1,%2,%3}, {%4,%5,%6,%7}, {%8,%9}, {%0,%1,%2,%3};"
        : "+f"(c[0]), "+f"(c[1]), "+f"(c[2]), "+f"(c[3])
        : "r"(a[0]), "r"(a[1]), "r"(a[2]), "r"(a[3]), "r"(b[0]), "r"(b[1]));
}

__device__ __forceinline__ unsigned s2u(const void* p) {
    unsigned r;
    asm("{.reg .u64 t; cvta.to.shared.u64 t, %1; cvt.u32.u64 %0, t;}" : "=r"(r) : "l"(p));
    return r;
}
__device__ __forceinline__ void cp16(unsigned smaddr, const void* g) {
    asm volatile("cp.async.cg.shared.global [%0], [%1], 16;" :: "r"(smaddr), "l"(g));
}
#define CP_COMMIT() asm volatile("cp.async.commit_group;" ::: "memory")
#define CP_WAIT1()  asm volatile("cp.async.wait_group 1;" ::: "memory")

// Warp computes C[wr0:wr0+32][wc0:wc0+NT*8] += A(:, koff:koff+K) @ B(K rows)
template <int NT, int SAs, int SBs, int K>
__device__ __forceinline__ void mma_stage_p(const unsigned* __restrict__ A,
                                            const unsigned* __restrict__ B,
                                            float acc[2][NT][4],
                                            int wr0, int wc0, int lane, int koff) {
    const int gr = lane >> 2, t2 = (lane & 3) * 2;
#pragma unroll
    for (int k0 = 0; k0 < K; k0 += 16) {
        unsigned ah[2][4], al[2][4];
#pragma unroll
        for (int rb = 0; rb < 2; rb++) {
            const unsigned* p0 = A + (wr0 + rb * 16 + gr) * SAs + koff + k0 + t2;
            const unsigned* p1 = A + (wr0 + rb * 16 + 8 + gr) * SAs + koff + k0 + t2;
            uint2 wa = *(const uint2*)p0;
            uint2 wb = *(const uint2*)p1;
            uint2 wc = *(const uint2*)(p0 + 8);
            uint2 wd = *(const uint2*)(p1 + 8);
            ah[rb][0] = __byte_perm(wa.x, wa.y, 0x5410); al[rb][0] = __byte_perm(wa.x, wa.y, 0x7632);
            ah[rb][1] = __byte_perm(wb.x, wb.y, 0x5410); al[rb][1] = __byte_perm(wb.x, wb.y, 0x7632);
            ah[rb][2] = __byte_perm(wc.x, wc.y, 0x5410); al[rb][2] = __byte_perm(wc.x, wc.y, 0x7632);
            ah[rb][3] = __byte_perm(wd.x, wd.y, 0x5410); al[rb][3] = __byte_perm(wd.x, wd.y, 0x7632);
        }
#pragma unroll
        for (int nt = 0; nt < NT; nt++) {
            int n = wc0 + nt * 8 + gr;
            unsigned v0 = B[(k0 + t2) * SBs + n];
            unsigned v1 = B[(k0 + t2 + 1) * SBs + n];
            unsigned v2 = B[(k0 + 8 + t2) * SBs + n];
            unsigned v3 = B[(k0 + 9 + t2) * SBs + n];
            unsigned bh[2] = {__byte_perm(v0, v1, 0x5410), __byte_perm(v2, v3, 0x5410)};
            unsigned bl[2] = {__byte_perm(v0, v1, 0x7632), __byte_perm(v2, v3, 0x7632)};
#pragma unroll
            for (int rb = 0; rb < 2; rb++) {
                mma_bf16(acc[rb][nt], ah[rb], bh);
                mma_bf16(acc[rb][nt], al[rb], bh);
                mma_bf16(acc[rb][nt], ah[rb], bl);
            }
        }
    }
}

// ----------------------------------------------------------------------------
// Prep kernels
// ----------------------------------------------------------------------------
__global__ void prep_G(const float* __restrict__ cqa_W, const float* __restrict__ cc_W) {
    __shared__ float s_col[DD];
    int col = blockIdx.x;
    int d = threadIdx.x;
    s_col[d] = cqa_W[d * (4 * DD) + col];
    __syncthreads();
    float s = 0.f;
#pragma unroll 4
    for (int j = 0; j < DD; j++) s += cc_W[d * (2 * DD) + j] * s_col[j];
    g_GWp[col * DD + d] = pack_bf(s);
}

__global__ void prep_qf(const float* __restrict__ qf) {
    int i = blockIdx.x * blockDim.x + threadIdx.x;
    if (i >= BB * DD * QQ) return;
    int q = i % QQ;
    int t = i / QQ;
    int d = t % DD;
    int b = t / DD;
    g_qfTp[i] = pack_bf(qf[((size_t)(b * QQ + q)) * DD + d]);
    g_qfp[i] = pack_bf(qf[i]);
}

// warp-per-row: pack vfeats + vfeats*mlu, and rc dot product, one pass
__global__ void prep_vf_rc(const float* __restrict__ vf, const float* __restrict__ w4mlu,
                           const float* __restrict__ w4C) {
    int row = blockIdx.x * 8 + (threadIdx.x >> 5);
    int lane = threadIdx.x & 31;
    float4 t = *(const float4*)(vf + (size_t)row * DD + lane * 4);
    float4 m = *(const float4*)(w4mlu + lane * 4);
    float4 w = *(const float4*)(w4C + lane * 4);
    unsigned* vp = g_vfp + (size_t)row * DD + lane * 4;
    unsigned* mp = g_vmlup + (size_t)row * DD + lane * 4;
    vp[0] = pack_bf(t.x); vp[1] = pack_bf(t.y); vp[2] = pack_bf(t.z); vp[3] = pack_bf(t.w);
    mp[0] = pack_bf(t.x * m.x); mp[1] = pack_bf(t.y * m.y);
    mp[2] = pack_bf(t.z * m.z); mp[3] = pack_bf(t.w * m.w);
    float s = t.x * w.x + t.y * w.y + t.z * w.z + t.w * w.w;
#pragma unroll
    for (int off = 16; off > 0; off >>= 1) s += __shfl_xor_sync(0xffffffffu, s, off);
    if (lane == 0) g_rc[row] = s;
}

__global__ void prep_cq(const float* __restrict__ qf, const float* __restrict__ w4Q) {
    int row = blockIdx.x * 8 + (threadIdx.x >> 5);
    int lane = threadIdx.x & 31;
    float4 t = *(const float4*)(qf + (size_t)row * DD + lane * 4);
    float4 w = *(const float4*)(w4Q + lane * 4);
    float s = t.x * w.x + t.y * w.y + t.z * w.z + t.w * w.w;
#pragma unroll
    for (int off = 16; off > 0; off >>= 1) s += __shfl_xor_sync(0xffffffffu, s, off);
    if (lane == 0) g_cq[row] = s;
}

__global__ void zero_k() {
    int i = blockIdx.x * blockDim.x + threadIdx.x;
    if (i < BB * QQ * DD) g_mid[i] = 0.f;
    if (i < BB * QQ) g_colsum[i] = 0.f;
}

__global__ void pack_mid() {
    int i = blockIdx.x * blockDim.x + threadIdx.x;
    if (i >= BB * QQ * DD) return;
    int q = (i >> 7) & (QQ - 1);
    int b = i >> 14;
    g_midp[i] = pack_bf(g_mid[i] * (1.f / g_colsum[b * QQ + q]));
}

// ----------------------------------------------------------------------------
// Pooled projection (+ folded cqa_b @ ccW1.T + cc_b)
// ----------------------------------------------------------------------------
__global__ void pooled_kernel(const float* __restrict__ qf, const float* __restrict__ qmask,
                              const float* __restrict__ wp, const float* __restrict__ cc_W,
                              const float* __restrict__ cc_b, const float* __restrict__ cqa_b) {
    __shared__ float sred[QQ];
    __shared__ float s_al[QQ];
    __shared__ float s_pool[DD];
    int b = blockIdx.x, t = threadIdx.x;

    const float* row = qf + (size_t)(b * QQ + t) * DD;
    float x = 0.f;
#pragma unroll 4
    for (int d = 0; d < DD; d++) x += row[d] * wp[d];
    x += (1.f - qmask[b * QQ + t]) * MASKV;

    sred[t] = x; __syncthreads();
    for (int s = 64; s > 0; s >>= 1) {
        if (t < s) sred[t] = fmaxf(sred[t], sred[t + s]);
        __syncthreads();
    }
    float m = sred[0]; __syncthreads();
    float e = __expf(x - m);
    sred[t] = e; __syncthreads();
    for (int s = 64; s > 0; s >>= 1) {
        if (t < s) sred[t] += sred[t + s];
        __syncthreads();
    }
    float inv = 1.f / sred[0];
    s_al[t] = e * inv; __syncthreads();

    float p = 0.f;
#pragma unroll 4
    for (int q = 0; q < QQ; q++) p += s_al[q] * qf[(size_t)(b * QQ + q) * DD + t];
    s_pool[t] = p; __syncthreads();

    float o = cc_b[t];
#pragma unroll 4
    for (int k = 0; k < DD; k++) {
        o += s_pool[k] * cc_W[t * (2 * DD) + DD + k];
        o += cqa_b[k] * cc_W[t * (2 * DD) + k];
    }
    g_pproj[b * DD + t] = o;
}

// ----------------------------------------------------------------------------
// Score kernel: E = exp(score), + masked column sums
// ----------------------------------------------------------------------------
__global__ __launch_bounds__(256) void score_kernel(const float* __restrict__ vmask) {
    extern __shared__ unsigned su[];
    unsigned* sAp = su;               // [64][SA]
    unsigned* sBp = su + CT * SA;     // [128][SB]

    int b = blockIdx.y, c0 = blockIdx.x * CT, tid = threadIdx.x;

    {
        const uint4* srcA = (const uint4*)(g_vmlup + (size_t)(b * CC + c0) * DD);
        for (int i = tid; i < CT * DD / 4; i += 256)
            *(uint4*)&sAp[(i >> 5) * SA + (i & 31) * 4] = srcA[i];
        const uint4* srcB = (const uint4*)(g_qfTp + (size_t)b * DD * QQ);
        for (int i = tid; i < DD * QQ / 4; i += 256)
            *(uint4*)&sBp[(i >> 5) * SB + (i & 31) * 4] = srcB[i];
    }
    __syncthreads();

    int warp = tid >> 5, lane = tid & 31;
    int gr = lane >> 2, tg = lane & 3;
    int wr0 = (warp & 1) * 32, wc0 = (warp >> 1) * 32;

    float acc[2][4][4];
#pragma unroll
    for (int rb = 0; rb < 2; rb++)
#pragma unroll
        for (int nt = 0; nt < 4; nt++)
#pragma unroll
            for (int j = 0; j < 4; j++) acc[rb][nt][j] = 0.f;

    mma_stage_p<4, SA, SB, 128>(sAp, sBp, acc, wr0, wc0, lane, 0);

    float vm[4];
    vm[0] = vmask[b * CC + c0 + wr0 + gr];
    vm[1] = vmask[b * CC + c0 + wr0 + gr + 8];
    vm[2] = vmask[b * CC + c0 + wr0 + gr + 16];
    vm[3] = vmask[b * CC + c0 + wr0 + gr + 24];

#pragma unroll
    for (int rb = 0; rb < 2; rb++) {
        int r = wr0 + rb * 16 + gr;
        float rc0 = g_rc[b * CC + c0 + r];
        float rc1 = g_rc[b * CC + c0 + r + 8];
#pragma unroll
        for (int nt = 0; nt < 4; nt++) {
            int q = wc0 + nt * 8 + 2 * tg;
            float cq0 = g_cq[b * QQ + q], cq1 = g_cq[b * QQ + q + 1];
            acc[rb][nt][0] = __expf(acc[rb][nt][0] + rc0 + cq0);
            acc[rb][nt][1] = __expf(acc[rb][nt][1] + rc0 + cq1);
            acc[rb][nt][2] = __expf(acc[rb][nt][2] + rc1 + cq0);
            acc[rb][nt][3] = __expf(acc[rb][nt][3] + rc1 + cq1);
            float* d0 = g_score + ((size_t)(b * CC + c0 + r)) * QQ + q;
            float* d1 = g_score + ((size_t)(b * CC + c0 + r + 8)) * QQ + q;
            *(float2*)d0 = make_float2(acc[rb][nt][0], acc[rb][nt][1]);
            *(float2*)d1 = make_float2(acc[rb][nt][2], acc[rb][nt][3]);
        }
    }

#pragma unroll
    for (int nt = 0; nt < 4; nt++) {
#pragma unroll
        for (int j = 0; j < 2; j++) {
            float cs = acc[0][nt][j] * vm[0] + acc[0][nt][j + 2] * vm[1] +
                       acc[1][nt][j] * vm[2] + acc[1][nt][j + 2] * vm[3];
            cs += __shfl_xor_sync(0xffffffffu, cs, 4);
            cs += __shfl_xor_sync(0xffffffffu, cs, 8);
            cs += __shfl_xor_sync(0xffffffffu, cs, 16);
            if (lane < 4)
                atomicAdd(&g_colsum[b * QQ + wc0 + nt * 8 + 2 * tg + j], cs);
        }
    }
}

// ----------------------------------------------------------------------------
// mid(unscaled)[q,d] = sum_c E[c,q]*vmask[c]*v[c,d]
// ----------------------------------------------------------------------------
__global__ __launch_bounds__(256) void mid_kernel(const float* __restrict__ vmask) {
    __shared__ unsigned u_stT[QQ * SMA];
    __shared__ unsigned u_v[16 * SB];
    int b = blockIdx.x, sp = blockIdx.y, tid = threadIdx.x;
    int cbase = sp * (CC / NSPLIT);
    int warp = tid >> 5, lane = tid & 31;
    int gr = lane >> 2, tg = lane & 3;
    int wr0 = (warp & 3) * 32, wc0 = (warp >> 2) * 64;

    float acc[2][8][4];
#pragma unroll
    for (int rb = 0; rb < 2; rb++)
#pragma unroll
        for (int nt = 0; nt < 8; nt++)
#pragma unroll
            for (int j = 0; j < 4; j++) acc[rb][nt][j] = 0.f;

    for (int cc0 = 0; cc0 < CC / NSPLIT; cc0 += 16) {
        __syncthreads();
        for (int i = tid; i < 16 * QQ; i += 256) {
            int kc = i >> 7, col = i & 127;
            int c = cbase + cc0 + kc;
            float e = g_score[((size_t)(b * CC + c)) * QQ + col] * vmask[b * CC + c];
            u_stT[col * SMA + kc] = pack_bf(e);
        }
        const uint4* sv = (const uint4*)(g_vfp + (size_t)(b * CC + cbase + cc0) * DD);
        for (int i = tid; i < 16 * DD / 4; i += 256)
            *(uint4*)&u_v[(i >> 5) * SB + (i & 31) * 4] = sv[i];
        __syncthreads();
        mma_stage_p<8, SMA, SB, 16>(u_stT, u_v, acc, wr0, wc0, lane, 0);
    }

#pragma unroll
    for (int rb = 0; rb < 2; rb++) {
        int q = wr0 + rb * 16 + gr;
#pragma unroll
        for (int nt = 0; nt < 8; nt++) {
            int d = wc0 + nt * 8 + 2 * tg;
            atomicAdd(&g_mid[(size_t)(b * QQ + q) * DD + d],     acc[rb][nt][0]);
            atomicAdd(&g_mid[(size_t)(b * QQ + q) * DD + d + 1], acc[rb][nt][1]);
            atomicAdd(&g_mid[(size_t)(b * QQ + q + 8) * DD + d],     acc[rb][nt][2]);
            atomicAdd(&g_mid[(size_t)(b * QQ + q + 8) * DD + d + 1], acc[rb][nt][3]);
        }
    }
}

// ----------------------------------------------------------------------------
// Mega-fused v3: cp.async double-buffered B halves, 12 pipelined MMA slots
// Slot s: B-matrix m = s>>1 (qf, midp, G0..G3), half h = s&1 (K rows h*64..)
// A per slot: [sc,sc, sc,sc, v,v, c2q,c2q, v*c2q,v*c2q, v*q2c,v*q2c]
// ----------------------------------------------------------------------------
__global__ __launch_bounds__(256, 1) void fused_kernel(const float* __restrict__ qmask,
                                                       float* __restrict__ out) {
    extern __shared__ unsigned su[];
    unsigned* u_sc  = su;                 // [64][SA] sc -> v*c2q
    unsigned* u_v   = u_sc + CT * SA;     // [64][SA]
    unsigned* u_c2q = u_v + CT * SA;      // [64][SA]
    unsigned* u_q2c = u_c2q + CT * SA;    // [64][SA] -> v*q2c
    unsigned* u_B   = u_q2c + CT * SA;    // 2 x [64][SB] ping-pong

    int b = blockIdx.y;
    int c0 = blockIdx.x * CT;
    int tid = threadIdx.x;
    int warp = tid >> 5, lane = tid & 31;
    int gr = lane >> 2, tg = lane & 3;
    int wr0 = (warp & 1) * 32, wc0 = (warp >> 1) * 32;

    const unsigned* bsrc[6];
    bsrc[0] = g_qfp + (size_t)b * QQ * DD;
    bsrc[1] = g_midp + (size_t)b * QQ * DD;
    bsrc[2] = g_GWp;
    bsrc[3] = g_GWp + DD * DD;
    bsrc[4] = g_GWp + 2 * DD * DD;
    bsrc[5] = g_GWp + 3 * DD * DD;

    // async fill of B half (64 rows x 128 words) into buffer buf
#define FILL_HALF(slot, buf)                                                     \
    {                                                                            \
        const unsigned* src_ = bsrc[(slot) >> 1] + (((slot) & 1) * 64) * DD;     \
        unsigned* dstb_ = u_B + (buf) * (64 * SB);                               \
        for (int i = tid; i < 64 * DD / 4; i += 256)                             \
            cp16(s2u(&dstb_[(i >> 5) * SB + (i & 31) * 4]), &src_[i * 4]);       \
    }

    // Prologue: group1 = {u_v fill, slot0}, group2 = {slot1}
    {
        const unsigned* vs = g_vfp + (size_t)(b * CC + c0) * DD;
        for (int i = tid; i < CT * DD / 4; i += 256)
            cp16(s2u(&u_v[(i >> 5) * SA + (i & 31) * 4]), &vs[i * 4]);
        FILL_HALF(0, 0)
        CP_COMMIT();
        FILL_HALF(1, 1)
        CP_COMMIT();
    }

    // Phase 0: row softmax from E -> packed u_sc (overlaps async fills)
    {
        float qm[4];
#pragma unroll
        for (int j = 0; j < 4; j++) qm[j] = qmask[b * QQ + lane + 32 * j];
#pragma unroll
        for (int rr = 0; rr < 8; rr++) {
            int r = warp * 8 + rr;
            const float* src = g_score + ((size_t)(b * CC + c0 + r)) * QQ;
            float em[4];
            float s = 0.f;
#pragma unroll
            for (int j = 0; j < 4; j++) { em[j] = src[lane + 32 * j] * qm[j]; s += em[j]; }
#pragma unroll
            for (int off = 16; off > 0; off >>= 1)
                s += __shfl_xor_sync(0xffffffffu, s, off);
            float inv = 1.f / s;
#pragma unroll
            for (int j = 0; j < 4; j++)
                u_sc[r * SA + lane + 32 * j] = pack_bf(em[j] * inv);
        }
    }

#define ZERO_ACC(A_)                                      \
    _Pragma("unroll") for (int rb = 0; rb < 2; rb++)      \
    _Pragma("unroll") for (int nt = 0; nt < 4; nt++)      \
    _Pragma("unroll") for (int j = 0; j < 4; j++) A_[rb][nt][j] = 0.f;

#define PACK_ACC(DST, A_)                                                       \
    _Pragma("unroll") for (int rb = 0; rb < 2; rb++) {                          \
        int r_ = wr0 + rb * 16 + gr;                                            \
        _Pragma("unroll") for (int nt = 0; nt < 4; nt++) {                      \
            int cI = wc0 + nt * 8 + 2 * tg;                                     \
            (DST)[r_ * SA + cI]           = pack_bf(A_[rb][nt][0]);             \
            (DST)[r_ * SA + cI + 1]       = pack_bf(A_[rb][nt][1]);             \
            (DST)[(r_ + 8) * SA + cI]     = pack_bf(A_[rb][nt][2]);             \
            (DST)[(r_ + 8) * SA + cI + 1] = pack_bf(A_[rb][nt][3]);             \
        }                                                                       \
    }

    float acc1[2][4][4], acc2[2][4][4], oacc[2][4][4];
    ZERO_ACC(acc1)
    ZERO_ACC(acc2)

    // ---- pipeline: 12 slots ----
#define SLOT(i, Atile, ACC)                                                     \
    CP_WAIT1();                                                                 \
    __syncthreads();                                                            \
    mma_stage_p<4, SA, SB, 64>(Atile, u_B + ((i) & 1) * (64 * SB), ACC,         \
                               wr0, wc0, lane, ((i) & 1) * 64);                 \
    __syncthreads();                                                            \
    if ((i) + 2 < 12) { FILL_HALF((i) + 2, (i) & 1) }                           \
    CP_COMMIT();

    SLOT(0, u_sc, acc1)
    SLOT(1, u_sc, acc1)
    // c2q complete -> pack into u_c2q (read at slots 6,7; syncs intervene)
    PACK_ACC(u_c2q, acc1)
    SLOT(2, u_sc, acc2)
    SLOT(3, u_sc, acc2)
    // q2c complete: v*q2c from regs -> u_q2c; v*c2q pass -> u_sc (sc dead)
#pragma unroll
    for (int rb = 0; rb < 2; rb++) {
        int r = wr0 + rb * 16 + gr;
#pragma unroll
        for (int nt = 0; nt < 4; nt++) {
            int cI = wc0 + nt * 8 + 2 * tg;
            u_q2c[r * SA + cI]           = pack_bf(unpack_bf(u_v[r * SA + cI]) * acc2[rb][nt][0]);
            u_q2c[r * SA + cI + 1]       = pack_bf(unpack_bf(u_v[r * SA + cI + 1]) * acc2[rb][nt][1]);
            u_q2c[(r + 8) * SA + cI]     = pack_bf(unpack_bf(u_v[(r + 8) * SA + cI]) * acc2[rb][nt][2]);
            u_q2c[(r + 8) * SA + cI + 1] = pack_bf(unpack_bf(u_v[(r + 8) * SA + cI + 1]) * acc2[rb][nt][3]);
        }
    }
    for (int i = tid; i < CT * DD; i += 256) {
        int a_ = (i >> 7) * SA + (i & 127);
        u_sc[a_] = pack_bf(unpack_bf(u_v[a_]) * unpack_bf(u_c2q[a_]));
    }
    // init output accumulator with pproj
#pragma unroll
    for (int rb = 0; rb < 2; rb++)
#pragma unroll
        for (int nt = 0; nt < 4; nt++) {
            int d = wc0 + nt * 8 + 2 * tg;
            float p0 = g_pproj[b * DD + d], p1 = g_pproj[b * DD + d + 1];
            oacc[rb][nt][0] = p0; oacc[rb][nt][1] = p1;
            oacc[rb][nt][2] = p0; oacc[rb][nt][3] = p1;
        }
    SLOT(4, u_v, oacc)
    SLOT(5, u_v, oacc)
    SLOT(6, u_c2q, oacc)
    SLOT(7, u_c2q, oacc)
    SLOT(8, u_sc, oacc)
    SLOT(9, u_sc, oacc)
    SLOT(10, u_q2c, oacc)
    SLOT(11, u_q2c, oacc)

    // epilogue: relu + store
#pragma unroll
    for (int rb = 0; rb < 2; rb++) {
        int r = wr0 + rb * 16 + gr;
#pragma unroll
        for (int nt = 0; nt < 4; nt++) {
            int d = wc0 + nt * 8 + 2 * tg;
            float* d0 = out + ((size_t)(b * CC + c0 + r)) * DD + d;
            float* d1 = out + ((size_t)(b * CC + c0 + r + 8)) * DD + d;
            *(float2*)d0 = make_float2(fmaxf(oacc[rb][nt][0], 0.f), fmaxf(oacc[rb][nt][1], 0.f));
            *(float2*)d1 = make_float2(fmaxf(oacc[rb][nt][2], 0.f), fmaxf(oacc[rb][nt][3], 0.f));
        }
    }
}

// ----------------------------------------------------------------------------
// Launch
// ----------------------------------------------------------------------------
extern "C" void kernel_launch(void* const* d_in, const int* in_sizes, int n_in,
                              void* d_out, int out_size) {
    const float* vfeats = (const float*)d_in[0];
    const float* qfeats = (const float*)d_in[1];
    const float* vmask  = (const float*)d_in[2];
    const float* qmask  = (const float*)d_in[3];
    const float* w4C    = (const float*)d_in[4];
    const float* w4Q    = (const float*)d_in[5];
    const float* w4mlu  = (const float*)d_in[6];
    const float* cqa_W  = (const float*)d_in[7];
    const float* cqa_b  = (const float*)d_in[8];
    const float* wp     = (const float*)d_in[9];
    const float* cc_W   = (const float*)d_in[10];
    const float* cc_b   = (const float*)d_in[11];
    float* out = (float*)d_out;

    const int SCORE_SMEM = (CT * SA + DD * SB) * (int)sizeof(unsigned);           // ~101 KB
    const int FUSED_SMEM = (4 * CT * SA + 2 * 64 * SB) * (int)sizeof(unsigned);   // ~200 KB
    cudaFuncSetAttribute(score_kernel, cudaFuncAttributeMaxDynamicSharedMemorySize, SCORE_SMEM);
    cudaFuncSetAttribute(fused_kernel, cudaFuncAttributeMaxDynamicSharedMemorySize, FUSED_SMEM);

    prep_G<<<4 * DD, DD>>>(cqa_W, cc_W);
    prep_qf<<<(BB * DD * QQ + 255) / 256, 256>>>(qfeats);
    prep_vf_rc<<<BB * CC / 8, 256>>>(vfeats, w4mlu, w4C);
    prep_cq<<<BB * QQ / 8, 256>>>(qfeats, w4Q);
    zero_k<<<(BB * QQ * DD + 255) / 256, 256>>>();
    pooled_kernel<<<BB, QQ>>>(qfeats, qmask, wp, cc_W, cc_b, cqa_b);
    score_kernel<<<dim3(CC / CT, BB), 256, SCORE_SMEM>>>(vmask);
    mid_kernel<<<dim3(BB, NSPLIT), 256>>>(vmask);
    pack_mid<<<(BB * QQ * DD + 255) / 256, 256>>>();
    fused_kernel<<<dim3(CC / CT, BB), 256, FUSED_SMEM>>>(qmask, out);
}